// round 3
// baseline (speedup 1.0000x reference)
#include <cuda_runtime.h>
#include <cuda_bf16.h>
#include <cstdint>
#include <math.h>

#define SEQ    2048
#define HEADS  16
#define HD     64
#define EMB    1024
#define BATCH  4
#define ROWS   (BATCH * SEQ)   // 8192
#define SCALE  0.125f
#define MASKP  (-50.0f)

// ---------------- scratch (__device__ globals: allocation-free rule) -------
__device__ float g_q[ROWS * EMB];
__device__ float g_k[ROWS * EMB];
__device__ float g_v[ROWS * EMB];
__device__ float g_a[ROWS * EMB];
__device__ __nv_bfloat16 g_xh[ROWS * EMB];
__device__ __nv_bfloat16 g_xl[ROWS * EMB];
__device__ __nv_bfloat16 g_ah[ROWS * EMB];
__device__ __nv_bfloat16 g_al[ROWS * EMB];
__device__ __nv_bfloat16 g_wth[4][EMB * EMB];  // transposed W, hi part
__device__ __nv_bfloat16 g_wtl[4][EMB * EMB];  // transposed W, lo part

// ---------------- base-target-legal PTX helpers ----------------------------
__device__ __forceinline__ uint32_t smem_u32(const void* p) {
    uint32_t a;
    asm("{ .reg .u64 t; cvta.to.shared.u64 t, %1; cvt.u32.u64 %0, t; }"
        : "=r"(a) : "l"(p));
    return a;
}
__device__ __forceinline__ void ldsm4(uint32_t& r0, uint32_t& r1,
                                      uint32_t& r2, uint32_t& r3, uint32_t a) {
    asm volatile("ldmatrix.sync.aligned.m8n8.x4.shared.b16 {%0,%1,%2,%3}, [%4];"
                 : "=r"(r0), "=r"(r1), "=r"(r2), "=r"(r3) : "r"(a));
}
__device__ __forceinline__ void mma16816(float* c, const uint32_t* a,
                                         uint32_t b0, uint32_t b1) {
    asm volatile("mma.sync.aligned.m16n8k16.row.col.f32.bf16.bf16.f32 "
                 "{%0,%1,%2,%3}, {%4,%5,%6,%7}, {%8,%9}, {%0,%1,%2,%3};"
                 : "+f"(c[0]), "+f"(c[1]), "+f"(c[2]), "+f"(c[3])
                 : "r"(a[0]), "r"(a[1]), "r"(a[2]), "r"(a[3]), "r"(b0), "r"(b1));
}
#define CP_ASYNC16(da, ga) \
    asm volatile("cp.async.cg.shared.global [%0], [%1], 16;" :: "r"(da), "l"(ga))
#define CP_COMMIT() asm volatile("cp.async.commit_group;" ::: "memory")
template <int N> __device__ __forceinline__ void cp_wait() {
    asm volatile("cp.async.wait_group %0;" :: "n"(N) : "memory");
}

// ---------------- split / transpose-split convert kernels ------------------
__global__ __launch_bounds__(256) void split_kernel(
    const float* __restrict__ in, __nv_bfloat16* __restrict__ hi,
    __nv_bfloat16* __restrict__ lo, int n4)
{
    int i = blockIdx.x * blockDim.x + threadIdx.x;
    if (i >= n4) return;
    float4 v = ((const float4*)in)[i];
    float f[4] = {v.x, v.y, v.z, v.w};
    __nv_bfloat16 h[4], l[4];
    #pragma unroll
    for (int j = 0; j < 4; ++j) {
        h[j] = __float2bfloat16(f[j]);
        l[j] = __float2bfloat16(f[j] - __bfloat162float(h[j]));
    }
    ((__nv_bfloat162*)hi)[2 * i]     = __nv_bfloat162(h[0], h[1]);
    ((__nv_bfloat162*)hi)[2 * i + 1] = __nv_bfloat162(h[2], h[3]);
    ((__nv_bfloat162*)lo)[2 * i]     = __nv_bfloat162(l[0], l[1]);
    ((__nv_bfloat162*)lo)[2 * i + 1] = __nv_bfloat162(l[2], l[3]);
}

// W[k][n] (EMB x EMB) -> Wt[n][k] split into hi/lo bf16
__global__ __launch_bounds__(256) void transpose_split_kernel(
    const float* __restrict__ W, __nv_bfloat16* __restrict__ th,
    __nv_bfloat16* __restrict__ tl)
{
    __shared__ float t[32][33];
    int n = blockIdx.x * 32 + threadIdx.x;
    int k = blockIdx.y * 32 + threadIdx.y;
    #pragma unroll
    for (int j = 0; j < 4; ++j)
        t[threadIdx.y + 8 * j][threadIdx.x] = W[(size_t)(k + 8 * j) * EMB + n];
    __syncthreads();
    int ko = blockIdx.y * 32 + threadIdx.x;
    int no = blockIdx.x * 32 + threadIdx.y;
    #pragma unroll
    for (int j = 0; j < 4; ++j) {
        float f = t[threadIdx.x][threadIdx.y + 8 * j];
        __nv_bfloat16 h = __float2bfloat16(f);
        th[(size_t)(no + 8 * j) * EMB + ko] = h;
        tl[(size_t)(no + 8 * j) * EMB + ko] = __float2bfloat16(f - __bfloat162float(h));
    }
}

// ---------------- mma.sync bf16-split GEMM ---------------------------------
// C[*,1024] = (Ah+Al)[*,1024] @ (Bh+Bl)[1024(N),1024(K)]^T, 3-term split.
#define BK      32
#define NCHUNK  (EMB / BK)           // 32
#define ROWB    ((BK + 8) * 2)       // 80 bytes/row (pad: conflict-free ldmatrix)
#define TILE_B  (128 * ROWB)         // 10240
#define STAGE_B (4 * TILE_B)         // 40960: Ah,Al,Bh,Bl
#define GSM_TOTAL (2 * STAGE_B)      // 81920

__global__ __launch_bounds__(256, 1) void gemm_mma(
    const __nv_bfloat16* __restrict__ Ah, const __nv_bfloat16* __restrict__ Al,
    const __nv_bfloat16* __restrict__ Bh, const __nv_bfloat16* __restrict__ Bl,
    float* __restrict__ C)
{
    extern __shared__ char smc[];
    const uint32_t sb = smem_u32(smc);
    const int tid  = threadIdx.x;
    const int lane = tid & 31, wid = tid >> 5;
    const int wm = (wid >> 2) * 64;      // warp m offset in tile
    const int wn = (wid & 3) * 32;       // warp n offset in tile
    const int bm = blockIdx.y * 128, bn = blockIdx.x * 128;

    const __nv_bfloat16* srcs[4] = {Ah, Al, Bh, Bl};
    const int rbase[4] = {bm, bm, bn, bn};

    // per-thread cp.async slots: 2 x (row, 16B-seg) per tile
    const int r0_ = (0 * 256 + tid) >> 2, s0_ = (0 * 256 + tid) & 3;
    const int r1_ = (1 * 256 + tid) >> 2, s1_ = (1 * 256 + tid) & 3;

    #define LOAD_CHUNK(k0, st) do {                                            \
        uint32_t base_ = sb + (st) * STAGE_B;                                  \
        _Pragma("unroll")                                                      \
        for (int t_ = 0; t_ < 4; ++t_) {                                       \
            const __nv_bfloat16* src_ =                                        \
                srcs[t_] + (size_t)rbase[t_] * EMB + (k0);                     \
            CP_ASYNC16(base_ + t_ * TILE_B + r0_ * ROWB + s0_ * 16,            \
                       src_ + (size_t)r0_ * EMB + s0_ * 8);                    \
            CP_ASYNC16(base_ + t_ * TILE_B + r1_ * ROWB + s1_ * 16,            \
                       src_ + (size_t)r1_ * EMB + s1_ * 8);                    \
        }                                                                      \
    } while (0)

    // ldmatrix address components (x4: lane -> matrix (lane>>3), row (lane&7))
    const int fr = ((lane >> 3) & 1) * 8 + (lane & 7);  // row within 16
    const int fk = (lane >> 4) * 8;                     // k half (0/8)

    float acc[4][4][4];
    #pragma unroll
    for (int i = 0; i < 4; ++i)
        #pragma unroll
        for (int j = 0; j < 4; ++j)
            #pragma unroll
            for (int e = 0; e < 4; ++e) acc[i][j][e] = 0.0f;

    LOAD_CHUNK(0, 0);
    CP_COMMIT();

    for (int c = 0; c < NCHUNK; ++c) {
        if (c + 1 < NCHUNK) {
            LOAD_CHUNK((c + 1) * BK, (c + 1) & 1);
            CP_COMMIT();
            cp_wait<1>();
        } else {
            cp_wait<0>();
        }
        __syncthreads();

        const uint32_t base = sb + (c & 1) * STAGE_B;
        #pragma unroll
        for (int ks = 0; ks < 2; ++ks) {
            const int kb = ks * 16 + fk;
            uint32_t ah[4][4], al[4][4], bh[2][4], bl[2][4];
            #pragma unroll
            for (int mt = 0; mt < 4; ++mt) {
                uint32_t ra = base + (wm + mt * 16 + fr) * ROWB + kb * 2;
                ldsm4(ah[mt][0], ah[mt][1], ah[mt][2], ah[mt][3], ra);
                ldsm4(al[mt][0], al[mt][1], al[mt][2], al[mt][3], ra + TILE_B);
            }
            #pragma unroll
            for (int p = 0; p < 2; ++p) {
                uint32_t rbq = base + 2 * TILE_B + (wn + p * 16 + fr) * ROWB + kb * 2;
                ldsm4(bh[p][0], bh[p][1], bh[p][2], bh[p][3], rbq);
                ldsm4(bl[p][0], bl[p][1], bl[p][2], bl[p][3], rbq + TILE_B);
            }
            #pragma unroll
            for (int mt = 0; mt < 4; ++mt)
                #pragma unroll
                for (int nt = 0; nt < 4; ++nt) {
                    const int p = nt >> 1, w = nt & 1;
                    mma16816(acc[mt][nt], ah[mt], bh[p][w], bh[p][2 + w]);
                    mma16816(acc[mt][nt], ah[mt], bl[p][w], bl[p][2 + w]);
                    mma16816(acc[mt][nt], al[mt], bh[p][w], bh[p][2 + w]);
                }
        }
        __syncthreads();
    }

    // epilogue: c0,c1 = (row g, col 2t,2t+1); c2,c3 = row g+8
    const int g = lane >> 2, tg = lane & 3;
    #pragma unroll
    for (int mt = 0; mt < 4; ++mt)
        #pragma unroll
        for (int nt = 0; nt < 4; ++nt) {
            float* p0 = C + (size_t)(bm + wm + mt * 16 + g) * EMB
                          + bn + wn + nt * 8 + tg * 2;
            *(float2*)p0 = make_float2(acc[mt][nt][0], acc[mt][nt][1]);
            *(float2*)(p0 + 8 * EMB) = make_float2(acc[mt][nt][2], acc[mt][nt][3]);
        }
    #undef LOAD_CHUNK
}

// ---------------- attention (fp32, unchanged from R1) ----------------------
__global__ __launch_bounds__(256) void attn_kernel(
    const float* __restrict__ Q, const float* __restrict__ K,
    const float* __restrict__ V, float* __restrict__ O)
{
    extern __shared__ float smf[];
    float* Qs = smf;
    float* Ks = smf + 64 * 65;
    float* Vs = smf + 2 * 64 * 65;
    float* Ps = smf + 3 * 64 * 65;
    float* rs = smf + 4 * 64 * 65;

    const int tid = threadIdx.x;
    const int tx  = tid & 15;
    const int ty  = tid >> 4;
    const int q0  = blockIdx.x * 64;
    const int h   = blockIdx.y;
    const int b   = blockIdx.z;

    const size_t slice = (size_t)b * SEQ * EMB + (size_t)h * HD;
    const float* Qg = Q + slice;
    const float* Kg = K + slice;
    const float* Vg = V + slice;
    float*       Og = O + slice;

    for (int i = tid; i < 64 * 64; i += 256) {
        int r = i >> 6, d = i & 63;
        Qs[r * 65 + d] = Qg[(size_t)(q0 + r) * EMB + d];
    }
    if (tid < 64) rs[tid] = 0.0f;

    float o[4][4];
    #pragma unroll
    for (int i = 0; i < 4; ++i)
        #pragma unroll
        for (int j = 0; j < 4; ++j) o[i][j] = 0.0f;

    for (int k0 = 0; k0 < SEQ; k0 += 64) {
        __syncthreads();
        for (int i = tid; i < 64 * 64; i += 256) {
            int r = i >> 6, d = i & 63;
            Ks[r * 65 + d] = Kg[(size_t)(k0 + r) * EMB + d];
            Vs[r * 65 + d] = Vg[(size_t)(k0 + r) * EMB + d];
        }
        __syncthreads();

        float s[4][4];
        #pragma unroll
        for (int i = 0; i < 4; ++i)
            #pragma unroll
            for (int j = 0; j < 4; ++j) s[i][j] = 0.0f;

        for (int d = 0; d < 64; ++d) {
            float qa[4], kb_[4];
            #pragma unroll
            for (int i = 0; i < 4; ++i) qa[i]  = Qs[(ty * 4 + i) * 65 + d];
            #pragma unroll
            for (int j = 0; j < 4; ++j) kb_[j] = Ks[(tx * 4 + j) * 65 + d];
            #pragma unroll
            for (int i = 0; i < 4; ++i)
                #pragma unroll
                for (int j = 0; j < 4; ++j)
                    s[i][j] += qa[i] * kb_[j];
        }

        #pragma unroll
        for (int i = 0; i < 4; ++i) {
            int qr = q0 + ty * 4 + i;
            #pragma unroll
            for (int j = 0; j < 4; ++j) {
                int kc = k0 + tx * 4 + j;
                float val = s[i][j] * SCALE + (kc > qr ? MASKP : 0.0f);
                Ps[(ty * 4 + i) * 65 + (tx * 4 + j)] = __expf(val);
            }
        }
        __syncthreads();

        if (tid < 64) {
            float sum = 0.0f;
            #pragma unroll 8
            for (int c = 0; c < 64; ++c) sum += Ps[tid * 65 + c];
            rs[tid] += sum;
        }

        for (int c = 0; c < 64; ++c) {
            float pv[4], vv[4];
            #pragma unroll
            for (int i = 0; i < 4; ++i) pv[i] = Ps[(ty * 4 + i) * 65 + c];
            #pragma unroll
            for (int j = 0; j < 4; ++j) vv[j] = Vs[c * 65 + tx * 4 + j];
            #pragma unroll
            for (int i = 0; i < 4; ++i)
                #pragma unroll
                for (int j = 0; j < 4; ++j)
                    o[i][j] += pv[i] * vv[j];
        }
    }
    __syncthreads();

    #pragma unroll
    for (int i = 0; i < 4; ++i) {
        float inv = 1.0f / rs[ty * 4 + i];
        #pragma unroll
        for (int j = 0; j < 4; ++j)
            Og[(size_t)(q0 + ty * 4 + i) * EMB + tx * 4 + j] = o[i][j] * inv;
    }
}

// ---------------------------------------------------------------------------
extern "C" void kernel_launch(void* const* d_in, const int* in_sizes, int n_in,
                              void* d_out, int out_size)
{
    const float* x  = (const float*)d_in[0];
    const float* Wq = (const float*)d_in[1];
    const float* Wk = (const float*)d_in[2];
    const float* Wv = (const float*)d_in[3];
    const float* Wr = (const float*)d_in[4];

    float *q, *k, *v, *a;
    cudaGetSymbolAddress((void**)&q, g_q);
    cudaGetSymbolAddress((void**)&k, g_k);
    cudaGetSymbolAddress((void**)&v, g_v);
    cudaGetSymbolAddress((void**)&a, g_a);
    __nv_bfloat16 *xh, *xl, *ah, *al, *wth, *wtl;
    cudaGetSymbolAddress((void**)&xh, g_xh);
    cudaGetSymbolAddress((void**)&xl, g_xl);
    cudaGetSymbolAddress((void**)&ah, g_ah);
    cudaGetSymbolAddress((void**)&al, g_al);
    cudaGetSymbolAddress((void**)&wth, g_wth);
    cudaGetSymbolAddress((void**)&wtl, g_wtl);

    cudaFuncSetAttribute(gemm_mma,
                         cudaFuncAttributeMaxDynamicSharedMemorySize, GSM_TOTAL);
    const int attn_smem = (4 * 64 * 65 + 64) * (int)sizeof(float);
    cudaFuncSetAttribute(attn_kernel,
                         cudaFuncAttributeMaxDynamicSharedMemorySize, attn_smem);

    // 1) convert inputs
    split_kernel<<<(ROWS * EMB / 4 + 255) / 256, 256>>>(x, xh, xl, ROWS * EMB / 4);
    const float* Ws[4] = {Wq, Wk, Wv, Wr};
    for (int i = 0; i < 4; ++i)
        transpose_split_kernel<<<dim3(32, 32), dim3(32, 8)>>>(
            Ws[i], wth + (size_t)i * EMB * EMB, wtl + (size_t)i * EMB * EMB);

    // 2) Q/K/V projections on tensor cores (mma.sync)
    dim3 ggrid(EMB / 128, ROWS / 128);  // (8, 64)
    gemm_mma<<<ggrid, 256, GSM_TOTAL>>>(xh, xl, wth + 0 * (size_t)EMB * EMB,
                                        wtl + 0 * (size_t)EMB * EMB, q);
    gemm_mma<<<ggrid, 256, GSM_TOTAL>>>(xh, xl, wth + 1 * (size_t)EMB * EMB,
                                        wtl + 1 * (size_t)EMB * EMB, k);
    gemm_mma<<<ggrid, 256, GSM_TOTAL>>>(xh, xl, wth + 2 * (size_t)EMB * EMB,
                                        wtl + 2 * (size_t)EMB * EMB, v);

    // 3) attention (fp32)
    attn_kernel<<<dim3(SEQ / 64, HEADS, BATCH), 256, attn_smem>>>(q, k, v, a);

    // 4) output projection
    split_kernel<<<(ROWS * EMB / 4 + 255) / 256, 256>>>(a, ah, al, ROWS * EMB / 4);
    gemm_mma<<<ggrid, 256, GSM_TOTAL>>>(ah, al, wth + 3 * (size_t)EMB * EMB,
                                        wtl + 3 * (size_t)EMB * EMB, (float*)d_out);
}

// round 9
// speedup vs baseline: 2.4295x; 2.4295x over previous
#include <cuda_runtime.h>
#include <cuda_fp16.h>
#include <cstdint>
#include <math.h>

#define SEQ    2048
#define HEADS  16
#define HD     64
#define EMB    1024
#define BATCH  4
#define ROWS   (BATCH * SEQ)   // 8192
#define SCALE  0.125f
#define MASKP  (-50.0f)

// Scratch (allocation-free rule: __device__ globals)
__device__ float g_q[ROWS * EMB];
__device__ float g_k[ROWS * EMB];
__device__ float g_v[ROWS * EMB];
__device__ float g_a[ROWS * EMB];

// ---------------- PTX helpers ----------------------------------------------
__device__ __forceinline__ uint32_t smem_u32(const void* p) {
    uint32_t a;
    asm("{ .reg .u64 t; cvta.to.shared.u64 t, %1; cvt.u32.u64 %0, t; }"
        : "=r"(a) : "l"(p));
    return a;
}
__device__ __forceinline__ void ldsm4(uint32_t& r0, uint32_t& r1,
                                      uint32_t& r2, uint32_t& r3, uint32_t a) {
    asm volatile("ldmatrix.sync.aligned.m8n8.x4.shared.b16 {%0,%1,%2,%3}, [%4];"
                 : "=r"(r0), "=r"(r1), "=r"(r2), "=r"(r3) : "r"(a));
}
__device__ __forceinline__ void mma_f16(float* c, const uint32_t* a,
                                        uint32_t b0, uint32_t b1) {
    asm volatile("mma.sync.aligned.m16n8k16.row.col.f32.f16.f16.f32 "
                 "{%0,%1,%2,%3}, {%4,%5,%6,%7}, {%8,%9}, {%0,%1,%2,%3};"
                 : "+f"(c[0]), "+f"(c[1]), "+f"(c[2]), "+f"(c[3])
                 : "r"(a[0]), "r"(a[1]), "r"(a[2]), "r"(a[3]), "r"(b0), "r"(b1));
}
__device__ __forceinline__ uint32_t pack_h2(float a, float b) {
    __half2 h = __floats2half2_rn(a, b);
    return (uint32_t)__half_as_ushort(__low2half(h)) |
           ((uint32_t)__half_as_ushort(__high2half(h)) << 16);
}

// ---------------------------------------------------------------------------
// R1 fp32 sgemm (proven): 128x128x8, 256 threads, 8x8 microtile.
// ---------------------------------------------------------------------------
__global__ __launch_bounds__(256) void sgemm_128x128(
    const float* __restrict__ A, const float* __restrict__ B,
    float* __restrict__ C, int M, int N, int K)
{
    __shared__ float As[8][128];
    __shared__ float Bs[8][128];

    const int tid = threadIdx.x;
    const int tx  = tid & 15;
    const int ty  = tid >> 4;
    const int bm  = blockIdx.y * 128;
    const int bn  = blockIdx.x * 128;

    const int am = tid >> 1;
    const int ak = (tid & 1) * 4;
    const int br = tid >> 5;
    const int bc = (tid & 31) * 4;

    const float* Ap = A + (size_t)(bm + am) * K + ak;
    const float* Bp = B + (size_t)br * N + bn + bc;

    float acc[8][8];
    #pragma unroll
    for (int i = 0; i < 8; ++i)
        #pragma unroll
        for (int j = 0; j < 8; ++j) acc[i][j] = 0.0f;

    for (int kb = 0; kb < K; kb += 8) {
        float4 a4 = *(const float4*)(Ap + kb);
        float4 b4 = *(const float4*)(Bp + (size_t)kb * N);
        As[ak + 0][am] = a4.x;
        As[ak + 1][am] = a4.y;
        As[ak + 2][am] = a4.z;
        As[ak + 3][am] = a4.w;
        *(float4*)&Bs[br][bc] = b4;
        __syncthreads();

        #pragma unroll
        for (int k = 0; k < 8; ++k) {
            float a[8], b[8];
            #pragma unroll
            for (int i = 0; i < 8; ++i) a[i] = As[k][ty * 8 + i];
            #pragma unroll
            for (int j = 0; j < 8; ++j) b[j] = Bs[k][tx * 8 + j];
            #pragma unroll
            for (int i = 0; i < 8; ++i)
                #pragma unroll
                for (int j = 0; j < 8; ++j)
                    acc[i][j] += a[i] * b[j];
        }
        __syncthreads();
    }

    #pragma unroll
    for (int i = 0; i < 8; ++i) {
        float* Cp = C + (size_t)(bm + ty * 8 + i) * N + bn + tx * 8;
        #pragma unroll
        for (int j = 0; j < 8; ++j) Cp[j] = acc[i][j];
    }
}

// ---------------------------------------------------------------------------
// FA2-style fp16 mma attention.
// CTA: 128 q-rows of one (b,h); 8 warps, each owns 16 q-rows (full width).
// K-tiles of 64. Scores small (|s|<~3) -> no max-subtraction; unnormalized O
// + row sums, divide at end. P stays in registers (score frag == A frag).
// Causal skip: tiles with k0 > q0+127 contribute ~e^-50 -> skipped.
// ---------------------------------------------------------------------------
#define TS 64
#define QROWPAD 72   // halves per smem row (144B = 9*16B: aligned, conflict-free)

__global__ __launch_bounds__(256, 2) void attn_mma(
    const float* __restrict__ Q, const float* __restrict__ K,
    const float* __restrict__ V, float* __restrict__ O)
{
    __shared__ __half Qs[128 * QROWPAD];
    __shared__ __half Ks[TS * QROWPAD];
    __shared__ __half Vt[HD * QROWPAD];   // V transposed: [d][s]

    const uint32_t sQ = smem_u32(Qs);
    const uint32_t sK = smem_u32(Ks);
    const uint32_t sV = smem_u32(Vt);

    const int tid  = threadIdx.x;
    const int lane = tid & 31, wid = tid >> 5;
    const int qblk = blockIdx.x, h = blockIdx.y, b = blockIdx.z;
    const int q0   = qblk * 128;

    const size_t slice = (size_t)b * SEQ * EMB + (size_t)h * HD;
    const float* Qg = Q + slice;
    const float* Kg = K + slice;
    const float* Vg = V + slice;
    float*       Og = O + slice;

    // --- load Q tile (128x64 fp32 -> fp16 smem): 128 rows x 16 float4 = 2048 ---
    #pragma unroll
    for (int it = 0; it < 8; ++it) {
        int v = it * 256 + tid;
        int r = v >> 4, seg = v & 15;           // 16 float4 per row
        float4 f = *(const float4*)(Qg + (size_t)(q0 + r) * EMB + seg * 4);
        __half2* dst = (__half2*)(Qs + r * QROWPAD + seg * 4);
        dst[0] = __floats2half2_rn(f.x, f.y);
        dst[1] = __floats2half2_rn(f.z, f.w);
    }
    __syncthreads();

    // --- Q fragments (loop-invariant) ---
    const int fr = ((lane >> 3) & 1) * 8 + (lane & 7);
    const int fk = (lane >> 4) * 8;
    uint32_t qf[4][4];
    #pragma unroll
    for (int ks = 0; ks < 4; ++ks) {
        uint32_t addr = sQ + ((wid * 16 + fr) * QROWPAD + ks * 16 + fk) * 2;
        ldsm4(qf[ks][0], qf[ks][1], qf[ks][2], qf[ks][3], addr);
    }

    float o[8][4];
    #pragma unroll
    for (int i = 0; i < 8; ++i)
        #pragma unroll
        for (int j = 0; j < 4; ++j) o[i][j] = 0.0f;
    float rs_lo = 0.0f, rs_hi = 0.0f;

    const int qr_lo = q0 + wid * 16 + (lane >> 2);
    const int qr_hi = qr_lo + 8;
    const int ntiles = (2 * qblk + 2 < SEQ / TS) ? 2 * qblk + 2 : SEQ / TS;

    for (int t = 0; t < ntiles; ++t) {
        const int k0 = t * TS;
        __syncthreads();   // previous tile's consumers done

        // load K tile (64x64 fp32 -> fp16): 64 rows x 16 float4 = 1024
        #pragma unroll
        for (int it = 0; it < 4; ++it) {
            int v = it * 256 + tid;
            int r = v >> 4, seg = v & 15;
            float4 f = *(const float4*)(Kg + (size_t)(k0 + r) * EMB + seg * 4);
            __half2* dst = (__half2*)(Ks + r * QROWPAD + seg * 4);
            dst[0] = __floats2half2_rn(f.x, f.y);
            dst[1] = __floats2half2_rn(f.z, f.w);
        }
        // load V tile transposed: thread reads V[s0..s0+3][d] -> Vt[d][s0..s0+3]
        #pragma unroll
        for (int it = 0; it < 4; ++it) {
            int v = it * 256 + tid;
            int d = v & 63, sg = v >> 6;        // 16 s-groups of 4
            int s0 = sg * 4;
            const float* vp = Vg + (size_t)(k0 + s0) * EMB + d;
            float f0 = vp[0], f1 = vp[EMB], f2 = vp[2 * EMB], f3 = vp[3 * EMB];
            __half2* dst = (__half2*)(Vt + d * QROWPAD + s0);
            dst[0] = __floats2half2_rn(f0, f1);
            dst[1] = __floats2half2_rn(f2, f3);
        }
        __syncthreads();

        // --- S = Q K^T (16 q-rows x 64 k-cols per warp) ---
        float sc[8][4];
        #pragma unroll
        for (int i = 0; i < 8; ++i)
            #pragma unroll
            for (int j = 0; j < 4; ++j) sc[i][j] = 0.0f;

        #pragma unroll
        for (int ks = 0; ks < 4; ++ks) {
            uint32_t bf[4][4];
            #pragma unroll
            for (int g = 0; g < 4; ++g) {
                uint32_t addr = sK + ((g * 16 + fr) * QROWPAD + ks * 16 + fk) * 2;
                ldsm4(bf[g][0], bf[g][1], bf[g][2], bf[g][3], addr);
            }
            #pragma unroll
            for (int nt = 0; nt < 8; ++nt)
                mma_f16(sc[nt], qf[ks], bf[nt >> 1][nt & 1], bf[nt >> 1][2 + (nt & 1)]);
        }

        // --- scale + causal(-50) + exp; pack P to fp16 frags; row sums ---
        uint32_t ph_lo[8], ph_hi[8];
        #pragma unroll
        for (int nt = 0; nt < 8; ++nt) {
            int kc = k0 + nt * 8 + 2 * (lane & 3);
            float p0 = __expf(sc[nt][0] * SCALE + (kc     > qr_lo ? MASKP : 0.0f));
            float p1 = __expf(sc[nt][1] * SCALE + (kc + 1 > qr_lo ? MASKP : 0.0f));
            float p2 = __expf(sc[nt][2] * SCALE + (kc     > qr_hi ? MASKP : 0.0f));
            float p3 = __expf(sc[nt][3] * SCALE + (kc + 1 > qr_hi ? MASKP : 0.0f));
            rs_lo += p0 + p1;
            rs_hi += p2 + p3;
            ph_lo[nt] = pack_h2(p0, p1);
            ph_hi[nt] = pack_h2(p2, p3);
        }

        // --- O += P @ V  (P from registers, V from Vt) ---
        #pragma unroll
        for (int j = 0; j < 4; ++j) {
            uint32_t af[4] = {ph_lo[2 * j], ph_hi[2 * j],
                              ph_lo[2 * j + 1], ph_hi[2 * j + 1]};
            uint32_t vf[4][4];
            #pragma unroll
            for (int g = 0; g < 4; ++g) {
                uint32_t addr = sV + ((g * 16 + fr) * QROWPAD + j * 16 + fk) * 2;
                ldsm4(vf[g][0], vf[g][1], vf[g][2], vf[g][3], addr);
            }
            #pragma unroll
            for (int nd = 0; nd < 8; ++nd)
                mma_f16(o[nd], af, vf[nd >> 1][nd & 1], vf[nd >> 1][2 + (nd & 1)]);
        }
    }

    // --- full row sums (quad reduce) + normalize + store fp32 ---
    rs_lo += __shfl_xor_sync(0xFFFFFFFF, rs_lo, 1);
    rs_lo += __shfl_xor_sync(0xFFFFFFFF, rs_lo, 2);
    rs_hi += __shfl_xor_sync(0xFFFFFFFF, rs_hi, 1);
    rs_hi += __shfl_xor_sync(0xFFFFFFFF, rs_hi, 2);
    const float il = 1.0f / rs_lo, ih = 1.0f / rs_hi;

    #pragma unroll
    for (int nd = 0; nd < 8; ++nd) {
        int dc = nd * 8 + 2 * (lane & 3);
        *(float2*)(Og + (size_t)qr_lo * EMB + dc) =
            make_float2(o[nd][0] * il, o[nd][1] * il);
        *(float2*)(Og + (size_t)qr_hi * EMB + dc) =
            make_float2(o[nd][2] * ih, o[nd][3] * ih);
    }
}

// ---------------------------------------------------------------------------
extern "C" void kernel_launch(void* const* d_in, const int* in_sizes, int n_in,
                              void* d_out, int out_size)
{
    const float* x  = (const float*)d_in[0];
    const float* Wq = (const float*)d_in[1];
    const float* Wk = (const float*)d_in[2];
    const float* Wv = (const float*)d_in[3];
    const float* Wr = (const float*)d_in[4];

    float *q, *k, *v, *a;
    cudaGetSymbolAddress((void**)&q, g_q);
    cudaGetSymbolAddress((void**)&k, g_k);
    cudaGetSymbolAddress((void**)&v, g_v);
    cudaGetSymbolAddress((void**)&a, g_a);

    dim3 ggrid(EMB / 128, ROWS / 128);  // (8, 64)

    sgemm_128x128<<<ggrid, 256>>>(x, Wq, q, ROWS, EMB, EMB);
    sgemm_128x128<<<ggrid, 256>>>(x, Wk, k, ROWS, EMB, EMB);
    sgemm_128x128<<<ggrid, 256>>>(x, Wv, v, ROWS, EMB, EMB);

    attn_mma<<<dim3(SEQ / 128, HEADS, BATCH), 256>>>(q, k, v, a);

    sgemm_128x128<<<ggrid, 256>>>(a, Wr, (float*)d_out, ROWS, EMB, EMB);
}

// round 10
// speedup vs baseline: 10.1640x; 4.1836x over previous
#include <cuda_runtime.h>
#include <cuda_fp16.h>
#include <cstdint>
#include <math.h>

#define SEQ    2048
#define HEADS  16
#define HD     64
#define EMB    1024
#define BATCH  4
#define ROWS   (BATCH * SEQ)   // 8192
#define SCALE  0.125f
#define MASKP  (-50.0f)

// Scratch (allocation-free rule: __device__ globals)
__device__ __half g_xh[ROWS * EMB];
__device__ __half g_qh[ROWS * EMB];
__device__ __half g_kh[ROWS * EMB];
__device__ __half g_vh[ROWS * EMB];
__device__ __half g_ah[ROWS * EMB];
__device__ __half g_wt[4][EMB * EMB];   // W transposed [N][K], fp16

// ---------------- PTX helpers ----------------------------------------------
__device__ __forceinline__ uint32_t smem_u32(const void* p) {
    uint32_t a;
    asm("{ .reg .u64 t; cvta.to.shared.u64 t, %1; cvt.u32.u64 %0, t; }"
        : "=r"(a) : "l"(p));
    return a;
}
__device__ __forceinline__ void ldsm4(uint32_t& r0, uint32_t& r1,
                                      uint32_t& r2, uint32_t& r3, uint32_t a) {
    asm volatile("ldmatrix.sync.aligned.m8n8.x4.shared.b16 {%0,%1,%2,%3}, [%4];"
                 : "=r"(r0), "=r"(r1), "=r"(r2), "=r"(r3) : "r"(a));
}
__device__ __forceinline__ void mma_f16(float* c, const uint32_t* a,
                                        uint32_t b0, uint32_t b1) {
    asm volatile("mma.sync.aligned.m16n8k16.row.col.f32.f16.f16.f32 "
                 "{%0,%1,%2,%3}, {%4,%5,%6,%7}, {%8,%9}, {%0,%1,%2,%3};"
                 : "+f"(c[0]), "+f"(c[1]), "+f"(c[2]), "+f"(c[3])
                 : "r"(a[0]), "r"(a[1]), "r"(a[2]), "r"(a[3]), "r"(b0), "r"(b1));
}
__device__ __forceinline__ uint32_t pack_h2(float a, float b) {
    __half2 h = __floats2half2_rn(a, b);
    return (uint32_t)__half_as_ushort(__low2half(h)) |
           ((uint32_t)__half_as_ushort(__high2half(h)) << 16);
}
#define CP_ASYNC16(da, ga) \
    asm volatile("cp.async.cg.shared.global [%0], [%1], 16;" :: "r"(da), "l"(ga))
#define CP_COMMIT() asm volatile("cp.async.commit_group;" ::: "memory")
template <int N> __device__ __forceinline__ void cp_wait() {
    asm volatile("cp.async.wait_group %0;" :: "n"(N) : "memory");
}

// ---------------- convert kernels ------------------------------------------
__global__ __launch_bounds__(256) void f2h_kernel(
    const float* __restrict__ in, __half* __restrict__ out, int n4)
{
    int i = blockIdx.x * blockDim.x + threadIdx.x;
    if (i >= n4) return;
    float4 v = ((const float4*)in)[i];
    __half2* dst = (__half2*)(out + 4 * (size_t)i);
    dst[0] = __floats2half2_rn(v.x, v.y);
    dst[1] = __floats2half2_rn(v.z, v.w);
}

// W[k][n] (EMB x EMB fp32) -> Wt[n][k] fp16
__global__ __launch_bounds__(256) void transpose_h_kernel(
    const float* __restrict__ W, __half* __restrict__ T)
{
    __shared__ float t[32][33];
    int n = blockIdx.x * 32 + threadIdx.x;
    int k = blockIdx.y * 32 + threadIdx.y;
    #pragma unroll
    for (int j = 0; j < 4; ++j)
        t[threadIdx.y + 8 * j][threadIdx.x] = W[(size_t)(k + 8 * j) * EMB + n];
    __syncthreads();
    int ko = blockIdx.y * 32 + threadIdx.x;
    int no = blockIdx.x * 32 + threadIdx.y;
    #pragma unroll
    for (int j = 0; j < 4; ++j)
        T[(size_t)(no + 8 * j) * EMB + ko] = __float2half(t[threadIdx.x][threadIdx.y + 8 * j]);
}

// ---------------------------------------------------------------------------
// fp16 mma GEMM: C[M,N] = A[M,K] @ Bt[N,K]^T. A,Bt half row-major.
// 128x128 tile, BK=32, cp.async double-buffer, 8 warps (warp tile 64x32).
// Fragment scheme identical to R3/R9 (numerically verified).
// ---------------------------------------------------------------------------
#define BKH     32
#define ROWBH   80                    // bytes per smem row (64B data + 16B pad)
#define TILEBH  (128 * ROWBH)         // 10240
#define STAGEBH (2 * TILEBH)          // 20480 (A + B)

template <bool HalfOut>
__global__ __launch_bounds__(256, 2) void hgemm(
    const __half* __restrict__ A, const __half* __restrict__ Bt, void* __restrict__ Cv)
{
    __shared__ __align__(16) char smh[2 * STAGEBH];   // 40960 B
    const uint32_t sb = smem_u32(smh);
    const int tid  = threadIdx.x;
    const int lane = tid & 31, wid = tid >> 5;
    const int wm = (wid >> 2) * 64;
    const int wn = (wid & 3) * 32;
    const int bm = blockIdx.y * 128, bn = blockIdx.x * 128;

    // load mapping: per tile 512 x 16B (128 rows x 4 segs); 2 per thread
    const int r0_ = tid >> 2,       s0_ = tid & 3;
    const int r1_ = (256 + tid) >> 2, s1_ = tid & 3;

    const __half* Ab = A  + (size_t)bm * EMB;
    const __half* Bb = Bt + (size_t)bn * EMB;

    #define LOADH(k0, st) do {                                                 \
        uint32_t base_ = sb + (st) * STAGEBH;                                  \
        CP_ASYNC16(base_ + r0_ * ROWBH + s0_ * 16,                             \
                   Ab + (size_t)r0_ * EMB + (k0) + s0_ * 8);                   \
        CP_ASYNC16(base_ + r1_ * ROWBH + s1_ * 16,                             \
                   Ab + (size_t)r1_ * EMB + (k0) + s1_ * 8);                   \
        CP_ASYNC16(base_ + TILEBH + r0_ * ROWBH + s0_ * 16,                    \
                   Bb + (size_t)r0_ * EMB + (k0) + s0_ * 8);                   \
        CP_ASYNC16(base_ + TILEBH + r1_ * ROWBH + s1_ * 16,                    \
                   Bb + (size_t)r1_ * EMB + (k0) + s1_ * 8);                   \
    } while (0)

    const int fr = ((lane >> 3) & 1) * 8 + (lane & 7);
    const int fk = (lane >> 4) * 8;

    float acc[4][4][4];
    #pragma unroll
    for (int i = 0; i < 4; ++i)
        #pragma unroll
        for (int j = 0; j < 4; ++j)
            #pragma unroll
            for (int e = 0; e < 4; ++e) acc[i][j][e] = 0.0f;

    LOADH(0, 0);
    CP_COMMIT();

    for (int c = 0; c < EMB / BKH; ++c) {
        if (c + 1 < EMB / BKH) {
            LOADH((c + 1) * BKH, (c + 1) & 1);
            CP_COMMIT();
            cp_wait<1>();
        } else {
            cp_wait<0>();
        }
        __syncthreads();

        const uint32_t base = sb + (c & 1) * STAGEBH;
        #pragma unroll
        for (int ks = 0; ks < 2; ++ks) {
            const int kb = ks * 16 + fk;
            uint32_t af[4][4], bf[2][4];
            #pragma unroll
            for (int mt = 0; mt < 4; ++mt) {
                uint32_t ra = base + (wm + mt * 16 + fr) * ROWBH + kb * 2;
                ldsm4(af[mt][0], af[mt][1], af[mt][2], af[mt][3], ra);
            }
            #pragma unroll
            for (int p = 0; p < 2; ++p) {
                uint32_t rb = base + TILEBH + (wn + p * 16 + fr) * ROWBH + kb * 2;
                ldsm4(bf[p][0], bf[p][1], bf[p][2], bf[p][3], rb);
            }
            #pragma unroll
            for (int mt = 0; mt < 4; ++mt)
                #pragma unroll
                for (int nt = 0; nt < 4; ++nt)
                    mma_f16(acc[mt][nt], af[mt], bf[nt >> 1][nt & 1], bf[nt >> 1][2 + (nt & 1)]);
        }
        __syncthreads();
    }

    const int g = lane >> 2, tg = lane & 3;
    #pragma unroll
    for (int mt = 0; mt < 4; ++mt)
        #pragma unroll
        for (int nt = 0; nt < 4; ++nt) {
            const size_t row = (size_t)(bm + wm + mt * 16 + g);
            const int    col = bn + wn + nt * 8 + tg * 2;
            if (HalfOut) {
                __half* C = (__half*)Cv;
                *(uint32_t*)(C + row * EMB + col) = pack_h2(acc[mt][nt][0], acc[mt][nt][1]);
                *(uint32_t*)(C + (row + 8) * EMB + col) = pack_h2(acc[mt][nt][2], acc[mt][nt][3]);
            } else {
                float* C = (float*)Cv;
                *(float2*)(C + row * EMB + col) = make_float2(acc[mt][nt][0], acc[mt][nt][1]);
                *(float2*)(C + (row + 8) * EMB + col) = make_float2(acc[mt][nt][2], acc[mt][nt][3]);
            }
        }
    #undef LOADH
}

// ---------------------------------------------------------------------------
// FA2-style fp16 mma attention (R9-proven), now with half I/O.
// ---------------------------------------------------------------------------
#define TS 64
#define QROWPAD 72   // halves per smem row (144B = 9*16B)

__global__ __launch_bounds__(256, 2) void attn_mma(
    const __half* __restrict__ Q, const __half* __restrict__ K,
    const __half* __restrict__ V, __half* __restrict__ O)
{
    __shared__ __align__(16) __half Qs[128 * QROWPAD];
    __shared__ __align__(16) __half Ks[TS * QROWPAD];
    __shared__ __align__(16) __half Vt[HD * QROWPAD];   // V transposed: [d][s]

    const uint32_t sQ = smem_u32(Qs);
    const uint32_t sK = smem_u32(Ks);
    const uint32_t sV = smem_u32(Vt);

    const int tid  = threadIdx.x;
    const int lane = tid & 31, wid = tid >> 5;
    const int qblk = blockIdx.x, h = blockIdx.y, b = blockIdx.z;
    const int q0   = qblk * 128;

    const size_t slice = (size_t)b * SEQ * EMB + (size_t)h * HD;
    const __half* Qg = Q + slice;
    const __half* Kg = K + slice;
    const __half* Vg = V + slice;
    __half*       Og = O + slice;

    // --- load Q tile (128 rows x 8 uint4) ---
    #pragma unroll
    for (int it = 0; it < 4; ++it) {
        int v = it * 256 + tid;
        int r = v >> 3, seg = v & 7;
        *(uint4*)(Qs + r * QROWPAD + seg * 8) =
            *(const uint4*)(Qg + (size_t)(q0 + r) * EMB + seg * 8);
    }
    __syncthreads();

    const int fr = ((lane >> 3) & 1) * 8 + (lane & 7);
    const int fk = (lane >> 4) * 8;
    uint32_t qf[4][4];
    #pragma unroll
    for (int ks = 0; ks < 4; ++ks) {
        uint32_t addr = sQ + ((wid * 16 + fr) * QROWPAD + ks * 16 + fk) * 2;
        ldsm4(qf[ks][0], qf[ks][1], qf[ks][2], qf[ks][3], addr);
    }

    float o[8][4];
    #pragma unroll
    for (int i = 0; i < 8; ++i)
        #pragma unroll
        for (int j = 0; j < 4; ++j) o[i][j] = 0.0f;
    float rs_lo = 0.0f, rs_hi = 0.0f;

    const int qr_lo = q0 + wid * 16 + (lane >> 2);
    const int qr_hi = qr_lo + 8;
    const int ntiles = (2 * qblk + 2 < SEQ / TS) ? 2 * qblk + 2 : SEQ / TS;

    for (int t = 0; t < ntiles; ++t) {
        const int k0 = t * TS;
        __syncthreads();

        // K tile: 64 rows x 8 uint4 = 512
        #pragma unroll
        for (int it = 0; it < 2; ++it) {
            int v = it * 256 + tid;
            int r = v >> 3, seg = v & 7;
            *(uint4*)(Ks + r * QROWPAD + seg * 8) =
                *(const uint4*)(Kg + (size_t)(k0 + r) * EMB + seg * 8);
        }
        // V transposed: Vt[d][s]
        #pragma unroll
        for (int it = 0; it < 4; ++it) {
            int v = it * 256 + tid;
            int d = v & 63, sg = v >> 6;
            int s0 = sg * 4;
            const __half* vp = Vg + (size_t)(k0 + s0) * EMB + d;
            __half2* dst = (__half2*)(Vt + d * QROWPAD + s0);
            dst[0] = __halves2half2(vp[0], vp[EMB]);
            dst[1] = __halves2half2(vp[2 * EMB], vp[3 * EMB]);
        }
        __syncthreads();

        // --- S = Q K^T ---
        float sc[8][4];
        #pragma unroll
        for (int i = 0; i < 8; ++i)
            #pragma unroll
            for (int j = 0; j < 4; ++j) sc[i][j] = 0.0f;

        #pragma unroll
        for (int ks = 0; ks < 4; ++ks) {
            uint32_t bf[4][4];
            #pragma unroll
            for (int g = 0; g < 4; ++g) {
                uint32_t addr = sK + ((g * 16 + fr) * QROWPAD + ks * 16 + fk) * 2;
                ldsm4(bf[g][0], bf[g][1], bf[g][2], bf[g][3], addr);
            }
            #pragma unroll
            for (int nt = 0; nt < 8; ++nt)
                mma_f16(sc[nt], qf[ks], bf[nt >> 1][nt & 1], bf[nt >> 1][2 + (nt & 1)]);
        }

        // --- scale + causal + exp; pack P; row sums ---
        uint32_t ph_lo[8], ph_hi[8];
        #pragma unroll
        for (int nt = 0; nt < 8; ++nt) {
            int kc = k0 + nt * 8 + 2 * (lane & 3);
            float p0 = __expf(sc[nt][0] * SCALE + (kc     > qr_lo ? MASKP : 0.0f));
            float p1 = __expf(sc[nt][1] * SCALE + (kc + 1 > qr_lo ? MASKP : 0.0f));
            float p2 = __expf(sc[nt][2] * SCALE + (kc     > qr_hi ? MASKP : 0.0f));
            float p3 = __expf(sc[nt][3] * SCALE + (kc + 1 > qr_hi ? MASKP : 0.0f));
            rs_lo += p0 + p1;
            rs_hi += p2 + p3;
            ph_lo[nt] = pack_h2(p0, p1);
            ph_hi[nt] = pack_h2(p2, p3);
        }

        // --- O += P @ V ---
        #pragma unroll
        for (int j = 0; j < 4; ++j) {
            uint32_t af[4] = {ph_lo[2 * j], ph_hi[2 * j],
                              ph_lo[2 * j + 1], ph_hi[2 * j + 1]};
            uint32_t vf[4][4];
            #pragma unroll
            for (int g = 0; g < 4; ++g) {
                uint32_t addr = sV + ((g * 16 + fr) * QROWPAD + j * 16 + fk) * 2;
                ldsm4(vf[g][0], vf[g][1], vf[g][2], vf[g][3], addr);
            }
            #pragma unroll
            for (int nd = 0; nd < 8; ++nd)
                mma_f16(o[nd], af, vf[nd >> 1][nd & 1], vf[nd >> 1][2 + (nd & 1)]);
        }
    }

    // --- row sums + normalize + store half ---
    rs_lo += __shfl_xor_sync(0xFFFFFFFF, rs_lo, 1);
    rs_lo += __shfl_xor_sync(0xFFFFFFFF, rs_lo, 2);
    rs_hi += __shfl_xor_sync(0xFFFFFFFF, rs_hi, 1);
    rs_hi += __shfl_xor_sync(0xFFFFFFFF, rs_hi, 2);
    const float il = 1.0f / rs_lo, ih = 1.0f / rs_hi;

    #pragma unroll
    for (int nd = 0; nd < 8; ++nd) {
        int dc = nd * 8 + 2 * (lane & 3);
        *(uint32_t*)(Og + (size_t)qr_lo * EMB + dc) = pack_h2(o[nd][0] * il, o[nd][1] * il);
        *(uint32_t*)(Og + (size_t)qr_hi * EMB + dc) = pack_h2(o[nd][2] * ih, o[nd][3] * ih);
    }
}

// ---------------------------------------------------------------------------
extern "C" void kernel_launch(void* const* d_in, const int* in_sizes, int n_in,
                              void* d_out, int out_size)
{
    const float* x  = (const float*)d_in[0];
    const float* Wq = (const float*)d_in[1];
    const float* Wk = (const float*)d_in[2];
    const float* Wv = (const float*)d_in[3];
    const float* Wr = (const float*)d_in[4];

    __half *xh, *qh, *kh, *vh, *ah, *wt;
    cudaGetSymbolAddress((void**)&xh, g_xh);
    cudaGetSymbolAddress((void**)&qh, g_qh);
    cudaGetSymbolAddress((void**)&kh, g_kh);
    cudaGetSymbolAddress((void**)&vh, g_vh);
    cudaGetSymbolAddress((void**)&ah, g_ah);
    cudaGetSymbolAddress((void**)&wt, g_wt);

    // converts
    f2h_kernel<<<(ROWS * EMB / 4 + 255) / 256, 256>>>(x, xh, ROWS * EMB / 4);
    const float* Ws[4] = {Wq, Wk, Wv, Wr};
    for (int i = 0; i < 4; ++i)
        transpose_h_kernel<<<dim3(32, 32), dim3(32, 8)>>>(Ws[i], wt + (size_t)i * EMB * EMB);

    dim3 ggrid(EMB / 128, ROWS / 128);  // (8, 64)

    hgemm<true><<<ggrid, 256>>>(xh, wt + 0 * (size_t)EMB * EMB, qh);
    hgemm<true><<<ggrid, 256>>>(xh, wt + 1 * (size_t)EMB * EMB, kh);
    hgemm<true><<<ggrid, 256>>>(xh, wt + 2 * (size_t)EMB * EMB, vh);

    attn_mma<<<dim3(SEQ / 128, HEADS, BATCH), 256>>>(qh, kh, vh, ah);

    hgemm<false><<<ggrid, 256>>>(ah, wt + 3 * (size_t)EMB * EMB, d_out);
}

// round 11
// speedup vs baseline: 11.9277x; 1.1735x over previous
#include <cuda_runtime.h>
#include <cuda_fp16.h>
#include <cstdint>
#include <math.h>

#define SEQ    2048
#define HEADS  16
#define HD     64
#define EMB    1024
#define BATCH  4
#define ROWS   (BATCH * SEQ)   // 8192
#define SCALE  0.125f
#define MASKP  (-50.0f)

// Scratch (allocation-free rule: __device__ globals)
__device__ __half g_xh[ROWS * EMB];
__device__ __half g_qh[ROWS * EMB];
__device__ __half g_kh[ROWS * EMB];
__device__ __half g_vh[ROWS * EMB];
__device__ __half g_ah[ROWS * EMB];
__device__ __half g_wt[4][EMB * EMB];   // W transposed [N][K] fp16; [0..2] = Wq|Wk|Wv fused

// ---------------- PTX helpers ----------------------------------------------
__device__ __forceinline__ uint32_t smem_u32(const void* p) {
    uint32_t a;
    asm("{ .reg .u64 t; cvta.to.shared.u64 t, %1; cvt.u32.u64 %0, t; }"
        : "=r"(a) : "l"(p));
    return a;
}
__device__ __forceinline__ void ldsm4(uint32_t& r0, uint32_t& r1,
                                      uint32_t& r2, uint32_t& r3, uint32_t a) {
    asm volatile("ldmatrix.sync.aligned.m8n8.x4.shared.b16 {%0,%1,%2,%3}, [%4];"
                 : "=r"(r0), "=r"(r1), "=r"(r2), "=r"(r3) : "r"(a));
}
__device__ __forceinline__ void mma_f16(float* c, const uint32_t* a,
                                        uint32_t b0, uint32_t b1) {
    asm volatile("mma.sync.aligned.m16n8k16.row.col.f32.f16.f16.f32 "
                 "{%0,%1,%2,%3}, {%4,%5,%6,%7}, {%8,%9}, {%0,%1,%2,%3};"
                 : "+f"(c[0]), "+f"(c[1]), "+f"(c[2]), "+f"(c[3])
                 : "r"(a[0]), "r"(a[1]), "r"(a[2]), "r"(a[3]), "r"(b0), "r"(b1));
}
__device__ __forceinline__ uint32_t pack_h2(float a, float b) {
    __half2 h = __floats2half2_rn(a, b);
    return (uint32_t)__half_as_ushort(__low2half(h)) |
           ((uint32_t)__half_as_ushort(__high2half(h)) << 16);
}
#define CP_ASYNC16(da, ga) \
    asm volatile("cp.async.cg.shared.global [%0], [%1], 16;" :: "r"(da), "l"(ga))
#define CP_COMMIT() asm volatile("cp.async.commit_group;" ::: "memory")
template <int N> __device__ __forceinline__ void cp_wait() {
    asm volatile("cp.async.wait_group %0;" :: "n"(N) : "memory");
}

// ---------------- convert kernels ------------------------------------------
__global__ __launch_bounds__(256) void f2h_kernel(
    const float* __restrict__ in, __half* __restrict__ out, int n4)
{
    int i = blockIdx.x * blockDim.x + threadIdx.x;
    if (i >= n4) return;
    float4 v = ((const float4*)in)[i];
    __half2* dst = (__half2*)(out + 4 * (size_t)i);
    dst[0] = __floats2half2_rn(v.x, v.y);
    dst[1] = __floats2half2_rn(v.z, v.w);
}

// 4 weights W[k][n] -> Wt[n][k] fp16, z-batched
__global__ __launch_bounds__(256) void transpose_h4_kernel(
    const float* __restrict__ W0, const float* __restrict__ W1,
    const float* __restrict__ W2, const float* __restrict__ W3,
    __half* __restrict__ T)
{
    __shared__ float t[32][33];
    const float* W = (blockIdx.z == 0) ? W0 : (blockIdx.z == 1) ? W1
                   : (blockIdx.z == 2) ? W2 : W3;
    __half* Tz = T + (size_t)blockIdx.z * EMB * EMB;
    int n = blockIdx.x * 32 + threadIdx.x;
    int k = blockIdx.y * 32 + threadIdx.y;
    #pragma unroll
    for (int j = 0; j < 4; ++j)
        t[threadIdx.y + 8 * j][threadIdx.x] = W[(size_t)(k + 8 * j) * EMB + n];
    __syncthreads();
    int ko = blockIdx.y * 32 + threadIdx.x;
    int no = blockIdx.x * 32 + threadIdx.y;
    #pragma unroll
    for (int j = 0; j < 4; ++j)
        Tz[(size_t)(no + 8 * j) * EMB + ko] =
            __float2half(t[threadIdx.x][threadIdx.y + 8 * j]);
}

// ---------------------------------------------------------------------------
// fp16 mma GEMM, BK=64, double-buffered cp.async, 8 warps (warp tile 64x32).
// MODE 0: fp32 out to C0 (N=1024).  MODE 1: half out routed to C0/C1/C2 by
// bn/1024 (fused QKV, N=3072).
// ---------------------------------------------------------------------------
#define BK2    64
#define ROWB2  144                    // 128B data + 16B pad (9x16B: conflict-free)
#define TILE2  (128 * ROWB2)          // 18432
#define STAGE2 (2 * TILE2)            // 36864 (A + B)
#define GSM2   (2 * STAGE2)           // 73728 dynamic

template <int MODE>
__global__ __launch_bounds__(256, 2) void hgemm2(
    const __half* __restrict__ A, const __half* __restrict__ Bt,
    void* __restrict__ C0, void* __restrict__ C1, void* __restrict__ C2)
{
    extern __shared__ __align__(16) char smh2[];
    const uint32_t sb = smem_u32(smh2);
    const int tid  = threadIdx.x;
    const int lane = tid & 31, wid = tid >> 5;
    const int wm = (wid >> 2) * 64;
    const int wn = (wid & 3) * 32;
    const int bm = blockIdx.y * 128, bn = blockIdx.x * 128;

    const __half* Ab = A  + (size_t)bm * EMB;
    const __half* Bb = Bt + (size_t)bn * EMB;

    // per tile: 128 rows x 8 segs of 16B = 1024 vecs; 4 per thread per tile
    #define LOADH2(k0, st) do {                                                \
        uint32_t base_ = sb + (st) * STAGE2;                                   \
        _Pragma("unroll")                                                      \
        for (int it_ = 0; it_ < 4; ++it_) {                                    \
            int v_ = it_ * 256 + tid;                                          \
            int r_ = v_ >> 3, s_ = v_ & 7;                                     \
            CP_ASYNC16(base_ + r_ * ROWB2 + s_ * 16,                           \
                       Ab + (size_t)r_ * EMB + (k0) + s_ * 8);                 \
            CP_ASYNC16(base_ + TILE2 + r_ * ROWB2 + s_ * 16,                   \
                       Bb + (size_t)r_ * EMB + (k0) + s_ * 8);                 \
        }                                                                      \
    } while (0)

    const int fr = ((lane >> 3) & 1) * 8 + (lane & 7);
    const int fk = (lane >> 4) * 8;

    float acc[4][4][4];
    #pragma unroll
    for (int i = 0; i < 4; ++i)
        #pragma unroll
        for (int j = 0; j < 4; ++j)
            #pragma unroll
            for (int e = 0; e < 4; ++e) acc[i][j][e] = 0.0f;

    LOADH2(0, 0);
    CP_COMMIT();

    for (int c = 0; c < EMB / BK2; ++c) {
        if (c + 1 < EMB / BK2) {
            LOADH2((c + 1) * BK2, (c + 1) & 1);
            CP_COMMIT();
            cp_wait<1>();
        } else {
            cp_wait<0>();
        }
        __syncthreads();

        const uint32_t base = sb + (c & 1) * STAGE2;
        #pragma unroll
        for (int ks = 0; ks < 4; ++ks) {
            const int kb = ks * 16 + fk;
            uint32_t af[4][4], bf[2][4];
            #pragma unroll
            for (int mt = 0; mt < 4; ++mt) {
                uint32_t ra = base + (wm + mt * 16 + fr) * ROWB2 + kb * 2;
                ldsm4(af[mt][0], af[mt][1], af[mt][2], af[mt][3], ra);
            }
            #pragma unroll
            for (int p = 0; p < 2; ++p) {
                uint32_t rb = base + TILE2 + (wn + p * 16 + fr) * ROWB2 + kb * 2;
                ldsm4(bf[p][0], bf[p][1], bf[p][2], bf[p][3], rb);
            }
            #pragma unroll
            for (int mt = 0; mt < 4; ++mt)
                #pragma unroll
                for (int nt = 0; nt < 4; ++nt)
                    mma_f16(acc[mt][nt], af[mt], bf[nt >> 1][nt & 1], bf[nt >> 1][2 + (nt & 1)]);
        }
        __syncthreads();
    }

    const int g = lane >> 2, tg = lane & 3;
    if (MODE == 1) {
        const int sel = bn >> 10;
        __half* C = (__half*)(sel == 0 ? C0 : sel == 1 ? C1 : C2);
        const int cb = (bn & 1023) + wn + tg * 2;
        #pragma unroll
        for (int mt = 0; mt < 4; ++mt)
            #pragma unroll
            for (int nt = 0; nt < 4; ++nt) {
                const size_t row = (size_t)(bm + wm + mt * 16 + g);
                *(uint32_t*)(C + row * EMB + cb + nt * 8) =
                    pack_h2(acc[mt][nt][0], acc[mt][nt][1]);
                *(uint32_t*)(C + (row + 8) * EMB + cb + nt * 8) =
                    pack_h2(acc[mt][nt][2], acc[mt][nt][3]);
            }
    } else {
        float* C = (float*)C0;
        const int cb = bn + wn + tg * 2;
        #pragma unroll
        for (int mt = 0; mt < 4; ++mt)
            #pragma unroll
            for (int nt = 0; nt < 4; ++nt) {
                const size_t row = (size_t)(bm + wm + mt * 16 + g);
                *(float2*)(C + row * EMB + cb + nt * 8) =
                    make_float2(acc[mt][nt][0], acc[mt][nt][1]);
                *(float2*)(C + (row + 8) * EMB + cb + nt * 8) =
                    make_float2(acc[mt][nt][2], acc[mt][nt][3]);
            }
    }
    #undef LOADH2
}

// ---------------------------------------------------------------------------
// FA2-style fp16 mma attention (R9/R10-proven), half I/O.
// ---------------------------------------------------------------------------
#define TS 64
#define QROWPAD 72   // halves per smem row (144B = 9*16B)

__global__ __launch_bounds__(256, 2) void attn_mma(
    const __half* __restrict__ Q, const __half* __restrict__ K,
    const __half* __restrict__ V, __half* __restrict__ O)
{
    __shared__ __align__(16) __half Qs[128 * QROWPAD];
    __shared__ __align__(16) __half Ks[TS * QROWPAD];
    __shared__ __align__(16) __half Vt[HD * QROWPAD];   // V transposed: [d][s]

    const uint32_t sQ = smem_u32(Qs);
    const uint32_t sK = smem_u32(Ks);
    const uint32_t sV = smem_u32(Vt);

    const int tid  = threadIdx.x;
    const int lane = tid & 31, wid = tid >> 5;
    const int qblk = blockIdx.x, h = blockIdx.y, b = blockIdx.z;
    const int q0   = qblk * 128;

    const size_t slice = (size_t)b * SEQ * EMB + (size_t)h * HD;
    const __half* Qg = Q + slice;
    const __half* Kg = K + slice;
    const __half* Vg = V + slice;
    __half*       Og = O + slice;

    #pragma unroll
    for (int it = 0; it < 4; ++it) {
        int v = it * 256 + tid;
        int r = v >> 3, seg = v & 7;
        *(uint4*)(Qs + r * QROWPAD + seg * 8) =
            *(const uint4*)(Qg + (size_t)(q0 + r) * EMB + seg * 8);
    }
    __syncthreads();

    const int fr = ((lane >> 3) & 1) * 8 + (lane & 7);
    const int fk = (lane >> 4) * 8;
    uint32_t qf[4][4];
    #pragma unroll
    for (int ks = 0; ks < 4; ++ks) {
        uint32_t addr = sQ + ((wid * 16 + fr) * QROWPAD + ks * 16 + fk) * 2;
        ldsm4(qf[ks][0], qf[ks][1], qf[ks][2], qf[ks][3], addr);
    }

    float o[8][4];
    #pragma unroll
    for (int i = 0; i < 8; ++i)
        #pragma unroll
        for (int j = 0; j < 4; ++j) o[i][j] = 0.0f;
    float rs_lo = 0.0f, rs_hi = 0.0f;

    const int qr_lo = q0 + wid * 16 + (lane >> 2);
    const int qr_hi = qr_lo + 8;
    const int ntiles = (2 * qblk + 2 < SEQ / TS) ? 2 * qblk + 2 : SEQ / TS;

    for (int t = 0; t < ntiles; ++t) {
        const int k0 = t * TS;
        __syncthreads();

        #pragma unroll
        for (int it = 0; it < 2; ++it) {
            int v = it * 256 + tid;
            int r = v >> 3, seg = v & 7;
            *(uint4*)(Ks + r * QROWPAD + seg * 8) =
                *(const uint4*)(Kg + (size_t)(k0 + r) * EMB + seg * 8);
        }
        #pragma unroll
        for (int it = 0; it < 4; ++it) {
            int v = it * 256 + tid;
            int d = v & 63, sg = v >> 6;
            int s0 = sg * 4;
            const __half* vp = Vg + (size_t)(k0 + s0) * EMB + d;
            __half2* dst = (__half2*)(Vt + d * QROWPAD + s0);
            dst[0] = __halves2half2(vp[0], vp[EMB]);
            dst[1] = __halves2half2(vp[2 * EMB], vp[3 * EMB]);
        }
        __syncthreads();

        float sc[8][4];
        #pragma unroll
        for (int i = 0; i < 8; ++i)
            #pragma unroll
            for (int j = 0; j < 4; ++j) sc[i][j] = 0.0f;

        #pragma unroll
        for (int ks = 0; ks < 4; ++ks) {
            uint32_t bf[4][4];
            #pragma unroll
            for (int g = 0; g < 4; ++g) {
                uint32_t addr = sK + ((g * 16 + fr) * QROWPAD + ks * 16 + fk) * 2;
                ldsm4(bf[g][0], bf[g][1], bf[g][2], bf[g][3], addr);
            }
            #pragma unroll
            for (int nt = 0; nt < 8; ++nt)
                mma_f16(sc[nt], qf[ks], bf[nt >> 1][nt & 1], bf[nt >> 1][2 + (nt & 1)]);
        }

        uint32_t ph_lo[8], ph_hi[8];
        #pragma unroll
        for (int nt = 0; nt < 8; ++nt) {
            int kc = k0 + nt * 8 + 2 * (lane & 3);
            float p0 = __expf(sc[nt][0] * SCALE + (kc     > qr_lo ? MASKP : 0.0f));
            float p1 = __expf(sc[nt][1] * SCALE + (kc + 1 > qr_lo ? MASKP : 0.0f));
            float p2 = __expf(sc[nt][2] * SCALE + (kc     > qr_hi ? MASKP : 0.0f));
            float p3 = __expf(sc[nt][3] * SCALE + (kc + 1 > qr_hi ? MASKP : 0.0f));
            rs_lo += p0 + p1;
            rs_hi += p2 + p3;
            ph_lo[nt] = pack_h2(p0, p1);
            ph_hi[nt] = pack_h2(p2, p3);
        }

        #pragma unroll
        for (int j = 0; j < 4; ++j) {
            uint32_t af[4] = {ph_lo[2 * j], ph_hi[2 * j],
                              ph_lo[2 * j + 1], ph_hi[2 * j + 1]};
            uint32_t vf[4][4];
            #pragma unroll
            for (int g = 0; g < 4; ++g) {
                uint32_t addr = sV + ((g * 16 + fr) * QROWPAD + j * 16 + fk) * 2;
                ldsm4(vf[g][0], vf[g][1], vf[g][2], vf[g][3], addr);
            }
            #pragma unroll
            for (int nd = 0; nd < 8; ++nd)
                mma_f16(o[nd], af, vf[nd >> 1][nd & 1], vf[nd >> 1][2 + (nd & 1)]);
        }
    }

    rs_lo += __shfl_xor_sync(0xFFFFFFFF, rs_lo, 1);
    rs_lo += __shfl_xor_sync(0xFFFFFFFF, rs_lo, 2);
    rs_hi += __shfl_xor_sync(0xFFFFFFFF, rs_hi, 1);
    rs_hi += __shfl_xor_sync(0xFFFFFFFF, rs_hi, 2);
    const float il = 1.0f / rs_lo, ih = 1.0f / rs_hi;

    #pragma unroll
    for (int nd = 0; nd < 8; ++nd) {
        int dc = nd * 8 + 2 * (lane & 3);
        *(uint32_t*)(Og + (size_t)qr_lo * EMB + dc) = pack_h2(o[nd][0] * il, o[nd][1] * il);
        *(uint32_t*)(Og + (size_t)qr_hi * EMB + dc) = pack_h2(o[nd][2] * ih, o[nd][3] * ih);
    }
}

// ---------------------------------------------------------------------------
extern "C" void kernel_launch(void* const* d_in, const int* in_sizes, int n_in,
                              void* d_out, int out_size)
{
    const float* x  = (const float*)d_in[0];
    const float* Wq = (const float*)d_in[1];
    const float* Wk = (const float*)d_in[2];
    const float* Wv = (const float*)d_in[3];
    const float* Wr = (const float*)d_in[4];

    __half *xh, *qh, *kh, *vh, *ah, *wt;
    cudaGetSymbolAddress((void**)&xh, g_xh);
    cudaGetSymbolAddress((void**)&qh, g_qh);
    cudaGetSymbolAddress((void**)&kh, g_kh);
    cudaGetSymbolAddress((void**)&vh, g_vh);
    cudaGetSymbolAddress((void**)&ah, g_ah);
    cudaGetSymbolAddress((void**)&wt, g_wt);

    cudaFuncSetAttribute(hgemm2<0>, cudaFuncAttributeMaxDynamicSharedMemorySize, GSM2);
    cudaFuncSetAttribute(hgemm2<1>, cudaFuncAttributeMaxDynamicSharedMemorySize, GSM2);

    // converts
    f2h_kernel<<<(ROWS * EMB / 4 + 255) / 256, 256>>>(x, xh, ROWS * EMB / 4);
    transpose_h4_kernel<<<dim3(32, 32, 4), dim3(32, 8)>>>(Wq, Wk, Wv, Wr, wt);

    // fused QKV projection: N = 3072
    hgemm2<1><<<dim3(24, 64), 256, GSM2>>>(xh, wt, qh, kh, vh);

    attn_mma<<<dim3(SEQ / 128, HEADS, BATCH), 256>>>(qh, kh, vh, ah);

    // output projection: fp32 out
    hgemm2<0><<<dim3(8, 64), 256, GSM2>>>(ah, wt + 3 * (size_t)EMB * EMB,
                                          d_out, nullptr, nullptr);
}

// round 14
// speedup vs baseline: 12.4104x; 1.0405x over previous
#include <cuda_runtime.h>
#include <cuda_fp16.h>
#include <cstdint>
#include <math.h>

#define SEQ    2048
#define HEADS  16
#define HD     64
#define EMB    1024
#define BATCH  4
#define ROWS   (BATCH * SEQ)   // 8192
#define SCALE  0.125f
#define MASKP  (-50.0f)

// Scratch (allocation-free rule: __device__ globals)
__device__ __half g_xh[ROWS * EMB];
__device__ __half g_qh[ROWS * EMB];
__device__ __half g_kh[ROWS * EMB];
__device__ __half g_vh[ROWS * EMB];
__device__ __half g_ah[ROWS * EMB];
__device__ __half g_wt[4][EMB * EMB];   // W transposed [N][K] fp16; [0..2] = Wq|Wk|Wv fused

// ---------------- PTX helpers ----------------------------------------------
__device__ __forceinline__ uint32_t smem_u32(const void* p) {
    uint32_t a;
    asm("{ .reg .u64 t; cvta.to.shared.u64 t, %1; cvt.u32.u64 %0, t; }"
        : "=r"(a) : "l"(p));
    return a;
}
__device__ __forceinline__ void ldsm4(uint32_t& r0, uint32_t& r1,
                                      uint32_t& r2, uint32_t& r3, uint32_t a) {
    asm volatile("ldmatrix.sync.aligned.m8n8.x4.shared.b16 {%0,%1,%2,%3}, [%4];"
                 : "=r"(r0), "=r"(r1), "=r"(r2), "=r"(r3) : "r"(a));
}
__device__ __forceinline__ void ldsm4t(uint32_t& r0, uint32_t& r1,
                                       uint32_t& r2, uint32_t& r3, uint32_t a) {
    asm volatile("ldmatrix.sync.aligned.m8n8.x4.trans.shared.b16 {%0,%1,%2,%3}, [%4];"
                 : "=r"(r0), "=r"(r1), "=r"(r2), "=r"(r3) : "r"(a));
}
__device__ __forceinline__ void mma_f16(float* c, const uint32_t* a,
                                        uint32_t b0, uint32_t b1) {
    asm volatile("mma.sync.aligned.m16n8k16.row.col.f32.f16.f16.f32 "
                 "{%0,%1,%2,%3}, {%4,%5,%6,%7}, {%8,%9}, {%0,%1,%2,%3};"
                 : "+f"(c[0]), "+f"(c[1]), "+f"(c[2]), "+f"(c[3])
                 : "r"(a[0]), "r"(a[1]), "r"(a[2]), "r"(a[3]), "r"(b0), "r"(b1));
}
__device__ __forceinline__ uint32_t pack_h2(float a, float b) {
    __half2 h = __floats2half2_rn(a, b);
    return (uint32_t)__half_as_ushort(__low2half(h)) |
           ((uint32_t)__half_as_ushort(__high2half(h)) << 16);
}
#define CP_ASYNC16(da, ga) \
    asm volatile("cp.async.cg.shared.global [%0], [%1], 16;" :: "r"(da), "l"(ga))
#define CP_COMMIT() asm volatile("cp.async.commit_group;" ::: "memory")
template <int N> __device__ __forceinline__ void cp_wait() {
    asm volatile("cp.async.wait_group %0;" :: "n"(N) : "memory");
}

// ---------------- convert kernels ------------------------------------------
__global__ __launch_bounds__(256) void f2h_kernel(
    const float* __restrict__ in, __half* __restrict__ out, int n4)
{
    int i = blockIdx.x * blockDim.x + threadIdx.x;
    if (i >= n4) return;
    float4 v = ((const float4*)in)[i];
    __half2* dst = (__half2*)(out + 4 * (size_t)i);
    dst[0] = __floats2half2_rn(v.x, v.y);
    dst[1] = __floats2half2_rn(v.z, v.w);
}

// 4 weights W[k][n] -> Wt[n][k] fp16, z-batched
__global__ __launch_bounds__(256) void transpose_h4_kernel(
    const float* __restrict__ W0, const float* __restrict__ W1,
    const float* __restrict__ W2, const float* __restrict__ W3,
    __half* __restrict__ T)
{
    __shared__ float t[32][33];
    const float* W = (blockIdx.z == 0) ? W0 : (blockIdx.z == 1) ? W1
                   : (blockIdx.z == 2) ? W2 : W3;
    __half* Tz = T + (size_t)blockIdx.z * EMB * EMB;
    int n = blockIdx.x * 32 + threadIdx.x;
    int k = blockIdx.y * 32 + threadIdx.y;
    #pragma unroll
    for (int j = 0; j < 4; ++j)
        t[threadIdx.y + 8 * j][threadIdx.x] = W[(size_t)(k + 8 * j) * EMB + n];
    __syncthreads();
    int ko = blockIdx.y * 32 + threadIdx.x;
    int no = blockIdx.x * 32 + threadIdx.y;
    #pragma unroll
    for (int j = 0; j < 4; ++j)
        Tz[(size_t)(no + 8 * j) * EMB + ko] =
            __float2half(t[threadIdx.x][threadIdx.y + 8 * j]);
}

// ---------------------------------------------------------------------------
// fp16 mma GEMM (R11-proven), BK=64, double-buffered cp.async, 8 warps.
// MODE 0: fp32 out (N=1024). MODE 1: half out routed by bn/1024 (QKV, N=3072).
// ---------------------------------------------------------------------------
#define BK2    64
#define ROWB2  144
#define TILE2  (128 * ROWB2)          // 18432
#define STAGE2 (2 * TILE2)            // 36864
#define GSM2   (2 * STAGE2)           // 73728

template <int MODE>
__global__ __launch_bounds__(256, 2) void hgemm2(
    const __half* __restrict__ A, const __half* __restrict__ Bt,
    void* __restrict__ C0, void* __restrict__ C1, void* __restrict__ C2)
{
    extern __shared__ __align__(16) char smh2[];
    const uint32_t sb = smem_u32(smh2);
    const int tid  = threadIdx.x;
    const int lane = tid & 31, wid = tid >> 5;
    const int wm = (wid >> 2) * 64;
    const int wn = (wid & 3) * 32;
    const int bm = blockIdx.y * 128, bn = blockIdx.x * 128;

    const __half* Ab = A  + (size_t)bm * EMB;
    const __half* Bb = Bt + (size_t)bn * EMB;

    #define LOADH2(k0, st) do {                                                \
        uint32_t base_ = sb + (st) * STAGE2;                                   \
        _Pragma("unroll")                                                      \
        for (int it_ = 0; it_ < 4; ++it_) {                                    \
            int v_ = it_ * 256 + tid;                                          \
            int r_ = v_ >> 3, s_ = v_ & 7;                                     \
            CP_ASYNC16(base_ + r_ * ROWB2 + s_ * 16,                           \
                       Ab + (size_t)r_ * EMB + (k0) + s_ * 8);                 \
            CP_ASYNC16(base_ + TILE2 + r_ * ROWB2 + s_ * 16,                   \
                       Bb + (size_t)r_ * EMB + (k0) + s_ * 8);                 \
        }                                                                      \
    } while (0)

    const int fr = ((lane >> 3) & 1) * 8 + (lane & 7);
    const int fk = (lane >> 4) * 8;

    float acc[4][4][4];
    #pragma unroll
    for (int i = 0; i < 4; ++i)
        #pragma unroll
        for (int j = 0; j < 4; ++j)
            #pragma unroll
            for (int e = 0; e < 4; ++e) acc[i][j][e] = 0.0f;

    LOADH2(0, 0);
    CP_COMMIT();

    for (int c = 0; c < EMB / BK2; ++c) {
        if (c + 1 < EMB / BK2) {
            LOADH2((c + 1) * BK2, (c + 1) & 1);
            CP_COMMIT();
            cp_wait<1>();
        } else {
            cp_wait<0>();
        }
        __syncthreads();

        const uint32_t base = sb + (c & 1) * STAGE2;
        #pragma unroll
        for (int ks = 0; ks < 4; ++ks) {
            const int kb = ks * 16 + fk;
            uint32_t af[4][4], bf[2][4];
            #pragma unroll
            for (int mt = 0; mt < 4; ++mt) {
                uint32_t ra = base + (wm + mt * 16 + fr) * ROWB2 + kb * 2;
                ldsm4(af[mt][0], af[mt][1], af[mt][2], af[mt][3], ra);
            }
            #pragma unroll
            for (int p = 0; p < 2; ++p) {
                uint32_t rb = base + TILE2 + (wn + p * 16 + fr) * ROWB2 + kb * 2;
                ldsm4(bf[p][0], bf[p][1], bf[p][2], bf[p][3], rb);
            }
            #pragma unroll
            for (int mt = 0; mt < 4; ++mt)
                #pragma unroll
                for (int nt = 0; nt < 4; ++nt)
                    mma_f16(acc[mt][nt], af[mt], bf[nt >> 1][nt & 1], bf[nt >> 1][2 + (nt & 1)]);
        }
        __syncthreads();
    }

    const int g = lane >> 2, tg = lane & 3;
    if (MODE == 1) {
        const int sel = bn >> 10;
        __half* C = (__half*)(sel == 0 ? C0 : sel == 1 ? C1 : C2);
        const int cb = (bn & 1023) + wn + tg * 2;
        #pragma unroll
        for (int mt = 0; mt < 4; ++mt)
            #pragma unroll
            for (int nt = 0; nt < 4; ++nt) {
                const size_t row = (size_t)(bm + wm + mt * 16 + g);
                *(uint32_t*)(C + row * EMB + cb + nt * 8) =
                    pack_h2(acc[mt][nt][0], acc[mt][nt][1]);
                *(uint32_t*)(C + (row + 8) * EMB + cb + nt * 8) =
                    pack_h2(acc[mt][nt][2], acc[mt][nt][3]);
            }
    } else {
        float* C = (float*)C0;
        const int cb = bn + wn + tg * 2;
        #pragma unroll
        for (int mt = 0; mt < 4; ++mt)
            #pragma unroll
            for (int nt = 0; nt < 4; ++nt) {
                const size_t row = (size_t)(bm + wm + mt * 16 + g);
                *(float2*)(C + row * EMB + cb + nt * 8) =
                    make_float2(acc[mt][nt][0], acc[mt][nt][1]);
                *(float2*)(C + (row + 8) * EMB + cb + nt * 8) =
                    make_float2(acc[mt][nt][2], acc[mt][nt][3]);
            }
    }
    #undef LOADH2
}

// ---------------------------------------------------------------------------
// FA2-style fp16 attention, v2: cp.async double-buffered K+V (row-major),
// ldmatrix.trans for the PV B-operand, mask-specialized tiles.
// CTA: 128 q-rows of one (b,h); 8 warps x 16 q-rows.
// ---------------------------------------------------------------------------
#define TS 64
#define ARP    72                       // halves per smem row (144 B)
#define ARPB   144
#define QBYTES (128 * ARPB)             // 18432
#define KVT    (TS * ARPB)              // 9216 per tile
#define ASTAGE (2 * KVT)                // 18432 (K + V)
#define ASMEM  (QBYTES + 2 * ASTAGE)    // 55296

__global__ __launch_bounds__(256, 2) void attn_mma(
    const __half* __restrict__ Q, const __half* __restrict__ K,
    const __half* __restrict__ V, __half* __restrict__ O)
{
    extern __shared__ __align__(16) char sma[];
    const uint32_t sQ = smem_u32(sma);

    const int tid  = threadIdx.x;
    const int lane = tid & 31, wid = tid >> 5;
    const int qblk = blockIdx.x, h = blockIdx.y, b = blockIdx.z;
    const int q0   = qblk * 128;

    const size_t slice = (size_t)b * SEQ * EMB + (size_t)h * HD;
    const __half* Qg = Q + slice;
    const __half* Kg = K + slice;
    const __half* Vg = V + slice;
    __half*       Og = O + slice;

    // --- Q tile: 128 rows x 8 x 16B via cp.async ---
    #pragma unroll
    for (int it = 0; it < 4; ++it) {
        int v = it * 256 + tid;
        int r = v >> 3, seg = v & 7;
        CP_ASYNC16(sQ + r * ARPB + seg * 16,
                   Qg + (size_t)(q0 + r) * EMB + seg * 8);
    }
    CP_COMMIT();

    // K/V tile loader: 64 rows x 8 x 16B each
    #define LOADKV(k0, st) do {                                                \
        uint32_t kb_ = sQ + QBYTES + (st) * ASTAGE;                            \
        _Pragma("unroll")                                                      \
        for (int it_ = 0; it_ < 2; ++it_) {                                    \
            int v_ = it_ * 256 + tid;                                          \
            int r_ = v_ >> 3, s_ = v_ & 7;                                     \
            CP_ASYNC16(kb_ + r_ * ARPB + s_ * 16,                              \
                       Kg + (size_t)((k0) + r_) * EMB + s_ * 8);               \
            CP_ASYNC16(kb_ + KVT + r_ * ARPB + s_ * 16,                        \
                       Vg + (size_t)((k0) + r_) * EMB + s_ * 8);               \
        }                                                                      \
    } while (0)

    LOADKV(0, 0);
    CP_COMMIT();

    const int fr = ((lane >> 3) & 1) * 8 + (lane & 7);
    const int fk = (lane >> 4) * 8;

    // --- Q fragments (wait for Q+KV0, then one barrier) ---
    cp_wait<0>();
    __syncthreads();
    uint32_t qf[4][4];
    #pragma unroll
    for (int ks = 0; ks < 4; ++ks) {
        uint32_t addr = sQ + (wid * 16 + fr) * ARPB + (ks * 16 + fk) * 2;
        ldsm4(qf[ks][0], qf[ks][1], qf[ks][2], qf[ks][3], addr);
    }

    float o[8][4];
    #pragma unroll
    for (int i = 0; i < 8; ++i)
        #pragma unroll
        for (int j = 0; j < 4; ++j) o[i][j] = 0.0f;
    float rs_lo = 0.0f, rs_hi = 0.0f;

    const int qr_lo = q0 + wid * 16 + (lane >> 2);
    const int qr_hi = qr_lo + 8;
    const int ntiles = 2 * qblk + 2;        // == min(2*qblk+2, SEQ/TS), exact here
    const int nfull  = 2 * qblk;            // tiles [0, nfull) are mask-free

    for (int t = 0; t < ntiles; ++t) {
        if (t + 1 < ntiles) {
            LOADKV((t + 1) * TS, (t + 1) & 1);
            CP_COMMIT();
            cp_wait<1>();
        } else {
            cp_wait<0>();
        }
        __syncthreads();

        const uint32_t sK = sQ + QBYTES + (t & 1) * ASTAGE;
        const uint32_t sV = sK + KVT;

        // --- S = Q K^T ---
        float sc[8][4];
        #pragma unroll
        for (int i = 0; i < 8; ++i)
            #pragma unroll
            for (int j = 0; j < 4; ++j) sc[i][j] = 0.0f;

        #pragma unroll
        for (int ks = 0; ks < 4; ++ks) {
            uint32_t bf[4][4];
            #pragma unroll
            for (int g = 0; g < 4; ++g) {
                uint32_t addr = sK + (g * 16 + fr) * ARPB + (ks * 16 + fk) * 2;
                ldsm4(bf[g][0], bf[g][1], bf[g][2], bf[g][3], addr);
            }
            #pragma unroll
            for (int nt = 0; nt < 8; ++nt)
                mma_f16(sc[nt], qf[ks], bf[nt >> 1][nt & 1], bf[nt >> 1][2 + (nt & 1)]);
        }

        // --- exp (+mask only on diagonal tiles); pack P; row sums ---
        uint32_t ph_lo[8], ph_hi[8];
        if (t < nfull) {
            #pragma unroll
            for (int nt = 0; nt < 8; ++nt) {
                float p0 = __expf(sc[nt][0] * SCALE);
                float p1 = __expf(sc[nt][1] * SCALE);
                float p2 = __expf(sc[nt][2] * SCALE);
                float p3 = __expf(sc[nt][3] * SCALE);
                rs_lo += p0 + p1;
                rs_hi += p2 + p3;
                ph_lo[nt] = pack_h2(p0, p1);
                ph_hi[nt] = pack_h2(p2, p3);
            }
        } else {
            const int kcb = t * TS + 2 * (lane & 3);
            #pragma unroll
            for (int nt = 0; nt < 8; ++nt) {
                int kc = kcb + nt * 8;
                float p0 = __expf(sc[nt][0] * SCALE + (kc     > qr_lo ? MASKP : 0.0f));
                float p1 = __expf(sc[nt][1] * SCALE + (kc + 1 > qr_lo ? MASKP : 0.0f));
                float p2 = __expf(sc[nt][2] * SCALE + (kc     > qr_hi ? MASKP : 0.0f));
                float p3 = __expf(sc[nt][3] * SCALE + (kc + 1 > qr_hi ? MASKP : 0.0f));
                rs_lo += p0 + p1;
                rs_hi += p2 + p3;
                ph_lo[nt] = pack_h2(p0, p1);
                ph_hi[nt] = pack_h2(p2, p3);
            }
        }

        // --- O += P @ V  (V row-major, B frags via ldmatrix.trans) ---
        #pragma unroll
        for (int j = 0; j < 4; ++j) {
            uint32_t af[4] = {ph_lo[2 * j], ph_hi[2 * j],
                              ph_lo[2 * j + 1], ph_hi[2 * j + 1]};
            #pragma unroll
            for (int g = 0; g < 4; ++g) {
                uint32_t vf0, vf1, vf2, vf3;
                uint32_t addr = sV + (j * 16 + fr) * ARPB + (g * 16 + fk) * 2;
                ldsm4t(vf0, vf1, vf2, vf3, addr);
                mma_f16(o[2 * g],     af, vf0, vf1);
                mma_f16(o[2 * g + 1], af, vf2, vf3);
            }
        }
        __syncthreads();   // all warps done with stage (t&1) before t+1 issues into (t+1)&1's partner
    }

    // --- row sums (quad reduce) + normalize + store half ---
    rs_lo += __shfl_xor_sync(0xFFFFFFFF, rs_lo, 1);
    rs_lo += __shfl_xor_sync(0xFFFFFFFF, rs_lo, 2);
    rs_hi += __shfl_xor_sync(0xFFFFFFFF, rs_hi, 1);
    rs_hi += __shfl_xor_sync(0xFFFFFFFF, rs_hi, 2);
    const float il = 1.0f / rs_lo, ih = 1.0f / rs_hi;

    #pragma unroll
    for (int nd = 0; nd < 8; ++nd) {
        int dc = nd * 8 + 2 * (lane & 3);
        *(uint32_t*)(Og + (size_t)qr_lo * EMB + dc) = pack_h2(o[nd][0] * il, o[nd][1] * il);
        *(uint32_t*)(Og + (size_t)qr_hi * EMB + dc) = pack_h2(o[nd][2] * ih, o[nd][3] * ih);
    }
    #undef LOADKV
}

// ---------------------------------------------------------------------------
extern "C" void kernel_launch(void* const* d_in, const int* in_sizes, int n_in,
                              void* d_out, int out_size)
{
    const float* x  = (const float*)d_in[0];
    const float* Wq = (const float*)d_in[1];
    const float* Wk = (const float*)d_in[2];
    const float* Wv = (const float*)d_in[3];
    const float* Wr = (const float*)d_in[4];

    __half *xh, *qh, *kh, *vh, *ah, *wt;
    cudaGetSymbolAddress((void**)&xh, g_xh);
    cudaGetSymbolAddress((void**)&qh, g_qh);
    cudaGetSymbolAddress((void**)&kh, g_kh);
    cudaGetSymbolAddress((void**)&vh, g_vh);
    cudaGetSymbolAddress((void**)&ah, g_ah);
    cudaGetSymbolAddress((void**)&wt, g_wt);

    cudaFuncSetAttribute(hgemm2<0>, cudaFuncAttributeMaxDynamicSharedMemorySize, GSM2);
    cudaFuncSetAttribute(hgemm2<1>, cudaFuncAttributeMaxDynamicSharedMemorySize, GSM2);
    cudaFuncSetAttribute(attn_mma,  cudaFuncAttributeMaxDynamicSharedMemorySize, ASMEM);

    // converts
    f2h_kernel<<<(ROWS * EMB / 4 + 255) / 256, 256>>>(x, xh, ROWS * EMB / 4);
    transpose_h4_kernel<<<dim3(32, 32, 4), dim3(32, 8)>>>(Wq, Wk, Wv, Wr, wt);

    // fused QKV projection: N = 3072
    hgemm2<1><<<dim3(24, 64), 256, GSM2>>>(xh, wt, qh, kh, vh);

    attn_mma<<<dim3(SEQ / 128, HEADS, BATCH), 256, ASMEM>>>(qh, kh, vh, ah);

    // output projection: fp32 out
    hgemm2<0><<<dim3(8, 64), 256, GSM2>>>(ah, wt + 3 * (size_t)EMB * EMB,
                                          d_out, nullptr, nullptr);
}

// round 15
// speedup vs baseline: 13.3937x; 1.0792x over previous
#include <cuda_runtime.h>
#include <cuda_fp16.h>
#include <cstdint>
#include <math.h>

#define SEQ    2048
#define HEADS  16
#define HD     64
#define EMB    1024
#define BATCH  4
#define ROWS   (BATCH * SEQ)   // 8192
#define SCALE  0.125f
#define MASKP  (-50.0f)
#define LOG2E  1.4426950408889634f
#define QC     (SCALE * LOG2E)          // folded into q at projection
#define MASK2  (MASKP * LOG2E)          // mask add in log2 domain

// Scratch (allocation-free rule: __device__ globals)
__device__ __half g_xh[ROWS * EMB];
__device__ __half g_qh[ROWS * EMB];
__device__ __half g_kh[ROWS * EMB];
__device__ __half g_vh[ROWS * EMB];
__device__ __half g_ah[ROWS * EMB];
__device__ __half g_wt[4][EMB * EMB];   // W transposed [N][K] fp16; [0..2] = Wq|Wk|Wv fused

// ---------------- PTX helpers ----------------------------------------------
__device__ __forceinline__ uint32_t smem_u32(const void* p) {
    uint32_t a;
    asm("{ .reg .u64 t; cvta.to.shared.u64 t, %1; cvt.u32.u64 %0, t; }"
        : "=r"(a) : "l"(p));
    return a;
}
__device__ __forceinline__ void ldsm4(uint32_t& r0, uint32_t& r1,
                                      uint32_t& r2, uint32_t& r3, uint32_t a) {
    asm volatile("ldmatrix.sync.aligned.m8n8.x4.shared.b16 {%0,%1,%2,%3}, [%4];"
                 : "=r"(r0), "=r"(r1), "=r"(r2), "=r"(r3) : "r"(a));
}
__device__ __forceinline__ void ldsm4t(uint32_t& r0, uint32_t& r1,
                                       uint32_t& r2, uint32_t& r3, uint32_t a) {
    asm volatile("ldmatrix.sync.aligned.m8n8.x4.trans.shared.b16 {%0,%1,%2,%3}, [%4];"
                 : "=r"(r0), "=r"(r1), "=r"(r2), "=r"(r3) : "r"(a));
}
__device__ __forceinline__ void mma_f16(float* c, const uint32_t* a,
                                        uint32_t b0, uint32_t b1) {
    asm volatile("mma.sync.aligned.m16n8k16.row.col.f32.f16.f16.f32 "
                 "{%0,%1,%2,%3}, {%4,%5,%6,%7}, {%8,%9}, {%0,%1,%2,%3};"
                 : "+f"(c[0]), "+f"(c[1]), "+f"(c[2]), "+f"(c[3])
                 : "r"(a[0]), "r"(a[1]), "r"(a[2]), "r"(a[3]), "r"(b0), "r"(b1));
}
__device__ __forceinline__ uint32_t pack_h2(float a, float b) {
    __half2 h = __floats2half2_rn(a, b);
    return (uint32_t)__half_as_ushort(__low2half(h)) |
           ((uint32_t)__half_as_ushort(__high2half(h)) << 16);
}
__device__ __forceinline__ uint32_t h2ex2(uint32_t a) {
    uint32_t d;
    asm volatile("ex2.approx.f16x2 %0, %1;" : "=r"(d) : "r"(a));
    return d;
}
#define CP_ASYNC16(da, ga) \
    asm volatile("cp.async.cg.shared.global [%0], [%1], 16;" :: "r"(da), "l"(ga))
#define CP_COMMIT() asm volatile("cp.async.commit_group;" ::: "memory")
template <int N> __device__ __forceinline__ void cp_wait() {
    asm volatile("cp.async.wait_group %0;" :: "n"(N) : "memory");
}

// ---------------- convert kernels ------------------------------------------
__global__ __launch_bounds__(256) void f2h_kernel(
    const float* __restrict__ in, __half* __restrict__ out, int n4)
{
    int i = blockIdx.x * blockDim.x + threadIdx.x;
    if (i >= n4) return;
    float4 v = ((const float4*)in)[i];
    __half2* dst = (__half2*)(out + 4 * (size_t)i);
    dst[0] = __floats2half2_rn(v.x, v.y);
    dst[1] = __floats2half2_rn(v.z, v.w);
}

// 4 weights W[k][n] -> Wt[n][k] fp16, z-batched
__global__ __launch_bounds__(256) void transpose_h4_kernel(
    const float* __restrict__ W0, const float* __restrict__ W1,
    const float* __restrict__ W2, const float* __restrict__ W3,
    __half* __restrict__ T)
{
    __shared__ float t[32][33];
    const float* W = (blockIdx.z == 0) ? W0 : (blockIdx.z == 1) ? W1
                   : (blockIdx.z == 2) ? W2 : W3;
    __half* Tz = T + (size_t)blockIdx.z * EMB * EMB;
    int n = blockIdx.x * 32 + threadIdx.x;
    int k = blockIdx.y * 32 + threadIdx.y;
    #pragma unroll
    for (int j = 0; j < 4; ++j)
        t[threadIdx.y + 8 * j][threadIdx.x] = W[(size_t)(k + 8 * j) * EMB + n];
    __syncthreads();
    int ko = blockIdx.y * 32 + threadIdx.x;
    int no = blockIdx.x * 32 + threadIdx.y;
    #pragma unroll
    for (int j = 0; j < 4; ++j)
        Tz[(size_t)(no + 8 * j) * EMB + ko] =
            __float2half(t[threadIdx.x][threadIdx.y + 8 * j]);
}

// ---------------------------------------------------------------------------
// fp16 mma GEMM (R11-proven), BK=64, double-buffered cp.async, 8 warps.
// MODE 0: fp32 out (N=1024). MODE 1: half out routed by bn/1024 (QKV, N=3072);
//         the q third (sel==0) is pre-scaled by QC = SCALE*log2e.
// ---------------------------------------------------------------------------
#define BK2    64
#define ROWB2  144
#define TILE2  (128 * ROWB2)          // 18432
#define STAGE2 (2 * TILE2)            // 36864
#define GSM2   (2 * STAGE2)           // 73728

template <int MODE>
__global__ __launch_bounds__(256, 2) void hgemm2(
    const __half* __restrict__ A, const __half* __restrict__ Bt,
    void* __restrict__ C0, void* __restrict__ C1, void* __restrict__ C2)
{
    extern __shared__ __align__(16) char smh2[];
    const uint32_t sb = smem_u32(smh2);
    const int tid  = threadIdx.x;
    const int lane = tid & 31, wid = tid >> 5;
    const int wm = (wid >> 2) * 64;
    const int wn = (wid & 3) * 32;
    const int bm = blockIdx.y * 128, bn = blockIdx.x * 128;

    const __half* Ab = A  + (size_t)bm * EMB;
    const __half* Bb = Bt + (size_t)bn * EMB;

    #define LOADH2(k0, st) do {                                                \
        uint32_t base_ = sb + (st) * STAGE2;                                   \
        _Pragma("unroll")                                                      \
        for (int it_ = 0; it_ < 4; ++it_) {                                    \
            int v_ = it_ * 256 + tid;                                          \
            int r_ = v_ >> 3, s_ = v_ & 7;                                     \
            CP_ASYNC16(base_ + r_ * ROWB2 + s_ * 16,                           \
                       Ab + (size_t)r_ * EMB + (k0) + s_ * 8);                 \
            CP_ASYNC16(base_ + TILE2 + r_ * ROWB2 + s_ * 16,                   \
                       Bb + (size_t)r_ * EMB + (k0) + s_ * 8);                 \
        }                                                                      \
    } while (0)

    const int fr = ((lane >> 3) & 1) * 8 + (lane & 7);
    const int fk = (lane >> 4) * 8;

    float acc[4][4][4];
    #pragma unroll
    for (int i = 0; i < 4; ++i)
        #pragma unroll
        for (int j = 0; j < 4; ++j)
            #pragma unroll
            for (int e = 0; e < 4; ++e) acc[i][j][e] = 0.0f;

    LOADH2(0, 0);
    CP_COMMIT();

    for (int c = 0; c < EMB / BK2; ++c) {
        if (c + 1 < EMB / BK2) {
            LOADH2((c + 1) * BK2, (c + 1) & 1);
            CP_COMMIT();
            cp_wait<1>();
        } else {
            cp_wait<0>();
        }
        __syncthreads();

        const uint32_t base = sb + (c & 1) * STAGE2;
        #pragma unroll
        for (int ks = 0; ks < 4; ++ks) {
            const int kb = ks * 16 + fk;
            uint32_t af[4][4], bf[2][4];
            #pragma unroll
            for (int mt = 0; mt < 4; ++mt) {
                uint32_t ra = base + (wm + mt * 16 + fr) * ROWB2 + kb * 2;
                ldsm4(af[mt][0], af[mt][1], af[mt][2], af[mt][3], ra);
            }
            #pragma unroll
            for (int p = 0; p < 2; ++p) {
                uint32_t rb = base + TILE2 + (wn + p * 16 + fr) * ROWB2 + kb * 2;
                ldsm4(bf[p][0], bf[p][1], bf[p][2], bf[p][3], rb);
            }
            #pragma unroll
            for (int mt = 0; mt < 4; ++mt)
                #pragma unroll
                for (int nt = 0; nt < 4; ++nt)
                    mma_f16(acc[mt][nt], af[mt], bf[nt >> 1][nt & 1], bf[nt >> 1][2 + (nt & 1)]);
        }
        __syncthreads();
    }

    const int g = lane >> 2, tg = lane & 3;
    if (MODE == 1) {
        const int sel = bn >> 10;
        __half* C = (__half*)(sel == 0 ? C0 : sel == 1 ? C1 : C2);
        const float fs = (sel == 0) ? QC : 1.0f;   // fold SCALE*log2e into q
        const int cb = (bn & 1023) + wn + tg * 2;
        #pragma unroll
        for (int mt = 0; mt < 4; ++mt)
            #pragma unroll
            for (int nt = 0; nt < 4; ++nt) {
                const size_t row = (size_t)(bm + wm + mt * 16 + g);
                *(uint32_t*)(C + row * EMB + cb + nt * 8) =
                    pack_h2(acc[mt][nt][0] * fs, acc[mt][nt][1] * fs);
                *(uint32_t*)(C + (row + 8) * EMB + cb + nt * 8) =
                    pack_h2(acc[mt][nt][2] * fs, acc[mt][nt][3] * fs);
            }
    } else {
        float* C = (float*)C0;
        const int cb = bn + wn + tg * 2;
        #pragma unroll
        for (int mt = 0; mt < 4; ++mt)
            #pragma unroll
            for (int nt = 0; nt < 4; ++nt) {
                const size_t row = (size_t)(bm + wm + mt * 16 + g);
                *(float2*)(C + row * EMB + cb + nt * 8) =
                    make_float2(acc[mt][nt][0], acc[mt][nt][1]);
                *(float2*)(C + (row + 8) * EMB + cb + nt * 8) =
                    make_float2(acc[mt][nt][2], acc[mt][nt][3]);
            }
    }
    #undef LOADH2
}

// ---------------------------------------------------------------------------
// FA2-style fp16 attention v3: 3-stage cp.async ring (1 barrier/tile),
// ex2.approx.f16x2 softmax (q pre-scaled by SCALE*log2e), row sums via
// all-ones MMA, ldmatrix.trans for PV.
// ---------------------------------------------------------------------------
#define TS 64
#define ARPB   144                      // bytes per smem row (128B data + 16B pad)
#define QBYTES (128 * ARPB)             // 18432
#define KVT    (TS * ARPB)              // 9216 per K or V tile
#define ASTAGE (2 * KVT)                // 18432 (K + V)
#define ASMEM  (QBYTES + 3 * ASTAGE)    // 73728

__global__ __launch_bounds__(256, 2) void attn_mma(
    const __half* __restrict__ Q, const __half* __restrict__ K,
    const __half* __restrict__ V, __half* __restrict__ O)
{
    extern __shared__ __align__(16) char sma[];
    const uint32_t sQ = smem_u32(sma);

    const int tid  = threadIdx.x;
    const int lane = tid & 31, wid = tid >> 5;
    const int qblk = blockIdx.x, h = blockIdx.y, b = blockIdx.z;
    const int q0   = qblk * 128;

    const size_t slice = (size_t)b * SEQ * EMB + (size_t)h * HD;
    const __half* Qg = Q + slice;
    const __half* Kg = K + slice;
    const __half* Vg = V + slice;
    __half*       Og = O + slice;

    #define LOADKV(k0, st) do {                                                \
        uint32_t kb_ = sQ + QBYTES + (st) * ASTAGE;                            \
        _Pragma("unroll")                                                      \
        for (int it_ = 0; it_ < 2; ++it_) {                                    \
            int v_ = it_ * 256 + tid;                                          \
            int r_ = v_ >> 3, s_ = v_ & 7;                                     \
            CP_ASYNC16(kb_ + r_ * ARPB + s_ * 16,                              \
                       Kg + (size_t)((k0) + r_) * EMB + s_ * 8);               \
            CP_ASYNC16(kb_ + KVT + r_ * ARPB + s_ * 16,                        \
                       Vg + (size_t)((k0) + r_) * EMB + s_ * 8);               \
        }                                                                      \
    } while (0)

    const int ntiles = 2 * qblk + 2;        // exact (== min(2*qblk+2, SEQ/TS))
    const int nfull  = 2 * qblk;            // tiles [0, nfull) are mask-free

    // --- prologue: Q + tile0 (group 0), tile1 (group 1) ---
    #pragma unroll
    for (int it = 0; it < 4; ++it) {
        int v = it * 256 + tid;
        int r = v >> 3, seg = v & 7;
        CP_ASYNC16(sQ + r * ARPB + seg * 16,
                   Qg + (size_t)(q0 + r) * EMB + seg * 8);
    }
    LOADKV(0, 0);
    CP_COMMIT();
    LOADKV(TS, 1);
    CP_COMMIT();

    const int fr = ((lane >> 3) & 1) * 8 + (lane & 7);
    const int fk = (lane >> 4) * 8;

    uint32_t qf[4][4];
    float o[8][4];
    #pragma unroll
    for (int i = 0; i < 8; ++i)
        #pragma unroll
        for (int j = 0; j < 4; ++j) o[i][j] = 0.0f;
    float rsacc[4] = {0.0f, 0.0f, 0.0f, 0.0f};
    const uint32_t ONE2 = 0x3C003C00u;      // half2(1.0, 1.0)

    const int qr_lo = q0 + wid * 16 + (lane >> 2);
    const int qr_hi = qr_lo + 8;

    for (int t = 0; t < ntiles; ++t) {
        // wait for tile t's group (allow newest, t+1, to remain pending)
        if (t + 1 < ntiles) cp_wait<1>(); else cp_wait<0>();
        __syncthreads();

        if (t == 0) {   // Q arrived with group 0
            #pragma unroll
            for (int ks = 0; ks < 4; ++ks) {
                uint32_t addr = sQ + (wid * 16 + fr) * ARPB + (ks * 16 + fk) * 2;
                ldsm4(qf[ks][0], qf[ks][1], qf[ks][2], qf[ks][3], addr);
            }
        }
        // issue tile t+2 into stage (t+2)%3 — safe: all warps past BAR(t),
        // hence done computing tile t-1 whose stage this overwrites
        if (t + 2 < ntiles) { LOADKV((t + 2) * TS, (t + 2) % 3); CP_COMMIT(); }

        const uint32_t sK = sQ + QBYTES + (t % 3) * ASTAGE;
        const uint32_t sV = sK + KVT;

        // --- S (in log2-domain: q pre-scaled) ---
        float sc[8][4];
        #pragma unroll
        for (int i = 0; i < 8; ++i)
            #pragma unroll
            for (int j = 0; j < 4; ++j) sc[i][j] = 0.0f;

        #pragma unroll
        for (int ks = 0; ks < 4; ++ks) {
            uint32_t bf[4][4];
            #pragma unroll
            for (int g = 0; g < 4; ++g) {
                uint32_t addr = sK + (g * 16 + fr) * ARPB + (ks * 16 + fk) * 2;
                ldsm4(bf[g][0], bf[g][1], bf[g][2], bf[g][3], addr);
            }
            #pragma unroll
            for (int nt = 0; nt < 8; ++nt)
                mma_f16(sc[nt], qf[ks], bf[nt >> 1][nt & 1], bf[nt >> 1][2 + (nt & 1)]);
        }

        // --- P = 2^sc via ex2.approx.f16x2 (mask only on diagonal tiles) ---
        uint32_t ph_lo[8], ph_hi[8];
        if (t < nfull) {
            #pragma unroll
            for (int nt = 0; nt < 8; ++nt) {
                ph_lo[nt] = h2ex2(pack_h2(sc[nt][0], sc[nt][1]));
                ph_hi[nt] = h2ex2(pack_h2(sc[nt][2], sc[nt][3]));
            }
        } else {
            const int kcb = t * TS + 2 * (lane & 3);
            #pragma unroll
            for (int nt = 0; nt < 8; ++nt) {
                int kc = kcb + nt * 8;
                float a0 = sc[nt][0] + (kc     > qr_lo ? MASK2 : 0.0f);
                float a1 = sc[nt][1] + (kc + 1 > qr_lo ? MASK2 : 0.0f);
                float a2 = sc[nt][2] + (kc     > qr_hi ? MASK2 : 0.0f);
                float a3 = sc[nt][3] + (kc + 1 > qr_hi ? MASK2 : 0.0f);
                ph_lo[nt] = h2ex2(pack_h2(a0, a1));
                ph_hi[nt] = h2ex2(pack_h2(a2, a3));
            }
        }

        // --- O += P @ V ; row sums via all-ones MMA ---
        #pragma unroll
        for (int j = 0; j < 4; ++j) {
            uint32_t af[4] = {ph_lo[2 * j], ph_hi[2 * j],
                              ph_lo[2 * j + 1], ph_hi[2 * j + 1]};
            #pragma unroll
            for (int g = 0; g < 4; ++g) {
                uint32_t vf0, vf1, vf2, vf3;
                uint32_t addr = sV + (j * 16 + fr) * ARPB + (g * 16 + fk) * 2;
                ldsm4t(vf0, vf1, vf2, vf3, addr);
                mma_f16(o[2 * g],     af, vf0, vf1);
                mma_f16(o[2 * g + 1], af, vf2, vf3);
            }
            mma_f16(rsacc, af, ONE2, ONE2);   // row sums (exact over k incl. lanes)
        }
    }

    // --- normalize + store half (rsacc[0]=sum(qr_lo), rsacc[2]=sum(qr_hi)) ---
    const float il = 1.0f / rsacc[0], ih = 1.0f / rsacc[2];

    #pragma unroll
    for (int nd = 0; nd < 8; ++nd) {
        int dc = nd * 8 + 2 * (lane & 3);
        *(uint32_t*)(Og + (size_t)qr_lo * EMB + dc) = pack_h2(o[nd][0] * il, o[nd][1] * il);
        *(uint32_t*)(Og + (size_t)qr_hi * EMB + dc) = pack_h2(o[nd][2] * ih, o[nd][3] * ih);
    }
    #undef LOADKV
}

// ---------------------------------------------------------------------------
extern "C" void kernel_launch(void* const* d_in, const int* in_sizes, int n_in,
                              void* d_out, int out_size)
{
    const float* x  = (const float*)d_in[0];
    const float* Wq = (const float*)d_in[1];
    const float* Wk = (const float*)d_in[2];
    const float* Wv = (const float*)d_in[3];
    const float* Wr = (const float*)d_in[4];

    __half *xh, *qh, *kh, *vh, *ah, *wt;
    cudaGetSymbolAddress((void**)&xh, g_xh);
    cudaGetSymbolAddress((void**)&qh, g_qh);
    cudaGetSymbolAddress((void**)&kh, g_kh);
    cudaGetSymbolAddress((void**)&vh, g_vh);
    cudaGetSymbolAddress((void**)&ah, g_ah);
    cudaGetSymbolAddress((void**)&wt, g_wt);

    cudaFuncSetAttribute(hgemm2<0>, cudaFuncAttributeMaxDynamicSharedMemorySize, GSM2);
    cudaFuncSetAttribute(hgemm2<1>, cudaFuncAttributeMaxDynamicSharedMemorySize, GSM2);
    cudaFuncSetAttribute(attn_mma,  cudaFuncAttributeMaxDynamicSharedMemorySize, ASMEM);

    // converts
    f2h_kernel<<<(ROWS * EMB / 4 + 255) / 256, 256>>>(x, xh, ROWS * EMB / 4);
    transpose_h4_kernel<<<dim3(32, 32, 4), dim3(32, 8)>>>(Wq, Wk, Wv, Wr, wt);

    // fused QKV projection: N = 3072 (q pre-scaled by SCALE*log2e)
    hgemm2<1><<<dim3(24, 64), 256, GSM2>>>(xh, wt, qh, kh, vh);

    attn_mma<<<dim3(SEQ / 128, HEADS, BATCH), 256, ASMEM>>>(qh, kh, vh, ah);

    // output projection: fp32 out
    hgemm2<0><<<dim3(8, 64), 256, GSM2>>>(ah, wt + 3 * (size_t)EMB * EMB,
                                          d_out, nullptr, nullptr);
}